// round 8
// baseline (speedup 1.0000x reference)
#include <cuda_runtime.h>
#include <cuda_bf16.h>
#include <math.h>
#include <stdint.h>

#define HW    16384
#define WIDTH 128
#define NB    8
#define CQKV  192

// ---------------- scratch (static device allocations; no cudaMalloc) --------
__device__ float    g_qkv[NB * CQKV * HW];    // 100.7 MB
__device__ float    g_d  [NB * CQKV * HW];    // 100.7 MB
__device__ uint32_t g_xh [NB * 128 * HW];     // x packed bf16-pair hi
__device__ uint32_t g_xl [NB * 128 * HW];
__device__ uint32_t g_oh [NB * 64 * HW];      // o packed hi
__device__ uint32_t g_ol [NB * 64 * HW];
__device__ uint32_t g_wqh[256 * 128], g_wql[256 * 128];   // qkv W padded to 256 rows
__device__ uint32_t g_wfh[256 * 64],  g_wfl[256 * 64];
__device__ float    g_kvp[NB * 16 * 8 * 72];

// ---------------- bf16 helpers ----------------------------------------------
__device__ __forceinline__ void bsplit(float x, float& h, float& l) {
    h = __bfloat162float(__float2bfloat16_rn(x));
    l = x - h;
}
__device__ __forceinline__ uint32_t bpack(float a, float b) {
    __nv_bfloat162 t = __floats2bfloat162_rn(a, b);
    return *reinterpret_cast<uint32_t*>(&t);
}
__device__ __forceinline__ void mma_bf16(float c[4], const uint32_t a[4], const uint32_t b[2]) {
    asm volatile(
        "mma.sync.aligned.m16n8k16.row.col.f32.bf16.bf16.f32 "
        "{%0,%1,%2,%3}, {%4,%5,%6,%7}, {%8,%9}, {%0,%1,%2,%3};\n"
        : "+f"(c[0]), "+f"(c[1]), "+f"(c[2]), "+f"(c[3])
        : "r"(a[0]), "r"(a[1]), "r"(a[2]), "r"(a[3]), "r"(b[0]), "r"(b[1]));
}
__device__ __forceinline__ uint32_t smem_u32(const void* p) {
    uint32_t a;
    asm("{ .reg .u64 t; cvta.to.shared.u64 t, %1; cvt.u32.u64 %0, t; }" : "=r"(a) : "l"(p));
    return a;
}
__device__ __forceinline__ void cpa16(uint32_t dst, const void* src) {
    asm volatile("cp.async.cg.shared.global [%0], [%1], 16;\n" :: "r"(dst), "l"(src));
}
#define CPA_COMMIT() asm volatile("cp.async.commit_group;\n" ::: "memory")
#define CPA_WAIT1()  asm volatile("cp.async.wait_group 1;\n" ::: "memory")
#define CPA_WAIT0()  asm volatile("cp.async.wait_group 0;\n" ::: "memory")

// ---------------- split kernels ---------------------------------------------
// W row-major MxK -> packed k-pair words; rows >= nvalid_pairs zero-padded
__global__ void wsplit_kernel(const float* __restrict__ W,
                              uint32_t* __restrict__ WH, uint32_t* __restrict__ WL,
                              int nvalid, int ntotal)
{
    int i = blockIdx.x * 256 + threadIdx.x;
    if (i >= ntotal) return;
    uint32_t hw = 0, lw = 0;
    if (i < nvalid) {
        float a = W[2 * i], b = W[2 * i + 1];
        float ha, la, hb, lb;
        bsplit(a, ha, la); bsplit(b, hb, lb);
        hw = bpack(ha, hb);
        lw = bpack(la, lb);
    }
    WH[i] = hw;
    WL[i] = lw;
}

// X [b][K][HW] -> packed k-pair arrays [b][K/2][HW]
__global__ void xsplit_kernel(const float* __restrict__ X,
                              uint32_t* __restrict__ XH, uint32_t* __restrict__ XL)
{
    int idx = blockIdx.x * 256 + threadIdx.x;
    int n  = (idx & 4095) * 4;
    int t  = idx >> 12;                           // b*128 + kp
    const float4 a = *(const float4*)&X[(size_t)t * 2 * HW + n];
    const float4 b = *(const float4*)&X[(size_t)t * 2 * HW + HW + n];
    const float av[4] = {a.x, a.y, a.z, a.w};
    const float bv[4] = {b.x, b.y, b.z, b.w};
    uint32_t hw[4], lw[4];
    #pragma unroll
    for (int j = 0; j < 4; j++) {
        float ha, la, hb, lb;
        bsplit(av[j], ha, la); bsplit(bv[j], hb, lb);
        hw[j] = bpack(ha, hb); lw[j] = bpack(la, lb);
    }
    *(uint4*)&XH[(size_t)t * HW + n] = make_uint4(hw[0], hw[1], hw[2], hw[3]);
    *(uint4*)&XL[(size_t)t * HW + n] = make_uint4(lw[0], lw[1], lw[2], lw[3]);
}

// ============ bf16x3 HMMA GEMM, 128x128 block, 64x64 warp tiles ============
// C[b](M x HW) = W(M x KTOT) * X[b](KTOT x HW)
// 128 threads = 4 warps (2x2), k32 chunks, double-buffered cp.async.
// MODE 0: plain store (guard rows >= MV). MODE 1: batchnorm affine.
template <int KTOT, int MODE>
__global__ void __launch_bounds__(128, 2)
hgemm(const uint32_t* __restrict__ AH, const uint32_t* __restrict__ AL,
      const uint32_t* __restrict__ BHg, const uint32_t* __restrict__ BLg,
      float* __restrict__ C, int MV,
      const float* __restrict__ gamma, const float* __restrict__ beta,
      const float* __restrict__ mean,  const float* __restrict__ var)
{
    constexpr int KP   = KTOT / 2;
    constexpr int NKIT = KTOT / 32;
    // stage layout (words): Ah[128][20]=2560, Al=2560, Bh[16][136]=2176, Bl=2176
    constexpr int SWRD = 9472;

    extern __shared__ uint32_t sm[];              // 2*SWRD = 75776 B
    const uint32_t smb = smem_u32(sm);

    const int tid  = threadIdx.x;
    const int lane = tid & 31;
    const int warp = tid >> 5;
    const int wm   = warp >> 1;                   // 0..1 -> 64 rows
    const int wn   = warp & 1;                    // 0..1 -> 64 cols
    const int g    = lane >> 2;
    const int tg   = lane & 3;

    const int m0 = blockIdx.y * 128;
    const int n0 = blockIdx.x * 128;
    const uint32_t* Bh = BHg + (size_t)blockIdx.z * KP * HW;
    const uint32_t* Bl = BLg + (size_t)blockIdx.z * KP * HW;
    float*          Cb = C   + (size_t)blockIdx.z * MV * HW;

    // loader roles
    const int arow = tid;                          // A: one row per thread
    const int brow = tid >> 3, bs = (tid & 7) * 16; // B: 16 kp-rows x 8 segs

    auto load_chunk = [&](int it, int stage) {
        const uint32_t s0 = smb + stage * SWRD * 4;
        const uint32_t* srcAh = AH + (size_t)(m0 + arow) * KP + it * 16;
        const uint32_t* srcAl = AL + (size_t)(m0 + arow) * KP + it * 16;
        uint32_t dA = s0 + (arow * 20) * 4;
        #pragma unroll
        for (int q = 0; q < 4; q++) {
            cpa16(dA + q * 16,            srcAh + q * 4);
            cpa16(dA + 2560 * 4 + q * 16, srcAl + q * 4);
        }
        const uint32_t* srcBh = Bh + (size_t)(it * 16 + brow) * HW + n0 + bs;
        const uint32_t* srcBl = Bl + (size_t)(it * 16 + brow) * HW + n0 + bs;
        uint32_t dB = s0 + (5120 + brow * 136 + bs) * 4;
        #pragma unroll
        for (int q = 0; q < 4; q++) {
            cpa16(dB + q * 16,            srcBh + q * 4);
            cpa16(dB + 2176 * 4 + q * 16, srcBl + q * 4);
        }
    };

    load_chunk(0, 0);
    CPA_COMMIT();

    float c[4][8][4] = {};

    for (int it = 0; it < NKIT; it++) {
        if (it + 1 < NKIT) { load_chunk(it + 1, (it + 1) & 1); CPA_COMMIT(); CPA_WAIT1(); }
        else               { CPA_WAIT0(); }
        __syncthreads();

        const uint32_t* sAh = sm + (it & 1) * SWRD;
        const uint32_t* sAl = sAh + 2560;
        const uint32_t* sBh = sAh + 5120;
        const uint32_t* sBl = sAh + 7296;

        #pragma unroll
        for (int ks = 0; ks < 2; ks++) {
            const int kp0 = ks * 8;
            uint32_t ah[4][4], al[4][4], bh[8][2], bl[8][2];
            #pragma unroll
            for (int mt = 0; mt < 4; mt++) {
                int r = wm * 64 + mt * 16 + g;
                ah[mt][0] = sAh[r * 20 + kp0 + tg];
                ah[mt][1] = sAh[(r + 8) * 20 + kp0 + tg];
                ah[mt][2] = sAh[r * 20 + kp0 + tg + 4];
                ah[mt][3] = sAh[(r + 8) * 20 + kp0 + tg + 4];
                al[mt][0] = sAl[r * 20 + kp0 + tg];
                al[mt][1] = sAl[(r + 8) * 20 + kp0 + tg];
                al[mt][2] = sAl[r * 20 + kp0 + tg + 4];
                al[mt][3] = sAl[(r + 8) * 20 + kp0 + tg + 4];
            }
            #pragma unroll
            for (int nt = 0; nt < 8; nt++) {
                int col = wn * 64 + nt * 8 + g;
                bh[nt][0] = sBh[(kp0 + tg) * 136 + col];
                bh[nt][1] = sBh[(kp0 + tg + 4) * 136 + col];
                bl[nt][0] = sBl[(kp0 + tg) * 136 + col];
                bl[nt][1] = sBl[(kp0 + tg + 4) * 136 + col];
            }
            // pass-wise: hh, hl, lh (32 independent accumulators per pass)
            #pragma unroll
            for (int nt = 0; nt < 8; nt++)
                #pragma unroll
                for (int mt = 0; mt < 4; mt++) mma_bf16(c[mt][nt], ah[mt], bh[nt]);
            #pragma unroll
            for (int nt = 0; nt < 8; nt++)
                #pragma unroll
                for (int mt = 0; mt < 4; mt++) mma_bf16(c[mt][nt], ah[mt], bl[nt]);
            #pragma unroll
            for (int nt = 0; nt < 8; nt++)
                #pragma unroll
                for (int mt = 0; mt < 4; mt++) mma_bf16(c[mt][nt], al[mt], bh[nt]);
        }
        __syncthreads();
    }

    // ---- epilogue: stage C tile in smem (stride 132), coalesced writeout ----
    float* Cs = (float*)sm;                       // 128*132 = 16896 w (fits)
    #pragma unroll
    for (int mt = 0; mt < 4; mt++)
        #pragma unroll
        for (int nt = 0; nt < 8; nt++) {
            int r   = wm * 64 + mt * 16 + g;
            int col = wn * 64 + nt * 8 + tg * 2;
            Cs[r * 132 + col]           = c[mt][nt][0];
            Cs[r * 132 + col + 1]       = c[mt][nt][1];
            Cs[(r + 8) * 132 + col]     = c[mt][nt][2];
            Cs[(r + 8) * 132 + col + 1] = c[mt][nt][3];
        }
    __syncthreads();

    for (int i = tid; i < 16384; i += 128) {
        int r = i >> 7, n = i & 127;
        int m = m0 + r;
        if (m >= MV) break;                       // rows sorted: all later i also out
        float v = Cs[r * 132 + n];
        if (MODE == 1) {
            float sc = __ldg(&gamma[m]) * rsqrtf(__ldg(&var[m]) + 1e-5f);
            v = v * sc + __ldg(&beta[m]) - __ldg(&mean[m]) * sc;
        }
        Cb[(size_t)m * HW + n0 + n] = v;
    }
}

// ---------------- fused p-mix + depthwise 3x3 (SAME, cross-correlation) -----
__global__ void __launch_bounds__(256)
pdw_kernel(const float* __restrict__ QKV,
           const float* __restrict__ Wp,
           const float* __restrict__ Wd,
           float* __restrict__ D)
{
    __shared__ float sin[8][4][WIDTH];
    __shared__ float sp [8][4][WIDTH];

    const int b  = blockIdx.z;
    const int gr = blockIdx.y;
    const int h0 = blockIdx.x * 2;
    const int tid = threadIdx.x;
    const float* src = QKV + ((size_t)b * CQKV + gr * 8) * HW;

    #pragma unroll
    for (int i = 0; i < 16; i++) {
        int lin = tid + i * 256;
        int ch = lin >> 9, rs = (lin >> 7) & 3, col = lin & 127;
        int row = h0 - 1 + rs;
        sin[ch][rs][col] = ((unsigned)row < (unsigned)WIDTH)
                           ? src[ch * HW + row * WIDTH + col] : 0.f;
    }
    __syncthreads();

    #pragma unroll
    for (int i = 0; i < 16; i++) {
        int lin = tid + i * 256;
        int oc = lin >> 9, rs = (lin >> 7) & 3, col = lin & 127;
        float s = 0.f;
        #pragma unroll
        for (int ic = 0; ic < 8; ic++)
            s += __ldg(&Wp[gr * 64 + oc * 8 + ic]) * sin[ic][rs][col];
        sp[oc][rs][col] = s;
    }
    __syncthreads();

    #pragma unroll
    for (int i = 0; i < 8; i++) {
        int lin = tid + i * 256;
        int oc = lin >> 8, hr = (lin >> 7) & 1, col = lin & 127;
        int c = gr * 8 + oc;
        float s = 0.f;
        #pragma unroll
        for (int ky = 0; ky < 3; ky++) {
            float w0 = __ldg(&Wd[c * 9 + ky * 3 + 0]);
            float w1 = __ldg(&Wd[c * 9 + ky * 3 + 1]);
            float w2 = __ldg(&Wd[c * 9 + ky * 3 + 2]);
            const float* row = sp[oc][hr + ky];
            if (col > 0)   s += w0 * row[col - 1];
            s += w1 * row[col];
            if (col < 127) s += w2 * row[col + 1];
        }
        D[((size_t)b * CQKV + c) * HW + (h0 + hr) * WIDTH + col] = s;
    }
}

// ---------------- kv partial sums -------------------------------------------
__global__ void __launch_bounds__(256)
kv_kernel(const float* __restrict__ QKV,
          const float* __restrict__ D,
          float* __restrict__ kvp)
{
    const int b = blockIdx.z, G = blockIdx.y, chunk = blockIdx.x;
    const int tid = threadIdx.x;
    const float* base = (G < 8) ? QKV + ((size_t)b * CQKV + G * 24) * HW
                                : D   + ((size_t)b * CQKV + (G - 8) * 24) * HW;
    float acc[72];
    #pragma unroll
    for (int i = 0; i < 72; i++) acc[i] = 0.f;

    #pragma unroll
    for (int it = 0; it < 4; it++) {
        int n = chunk * 2048 + it * 512 + tid * 2;
        float2 kr[8], vr[8];
        #pragma unroll
        for (int d = 0; d < 8; d++) {
            float2 t = *(const float2*)&base[(8 + d) * HW + n];
            kr[d].x = fmaxf(t.x, 0.f); kr[d].y = fmaxf(t.y, 0.f);
        }
        #pragma unroll
        for (int e = 0; e < 8; e++) vr[e] = *(const float2*)&base[(16 + e) * HW + n];
        #pragma unroll
        for (int d = 0; d < 8; d++) {
            #pragma unroll
            for (int e = 0; e < 8; e++)
                acc[d * 9 + e] += kr[d].x * vr[e].x + kr[d].y * vr[e].y;
            acc[d * 9 + 8] += kr[d].x + kr[d].y;
        }
    }

    __shared__ float red[8][72];
    const int lane = tid & 31, warp = tid >> 5;
    #pragma unroll
    for (int i = 0; i < 72; i++) {
        float v = acc[i];
        #pragma unroll
        for (int off = 16; off; off >>= 1) v += __shfl_down_sync(0xffffffffu, v, off);
        if (lane == 0) red[warp][i] = v;
    }
    __syncthreads();
    for (int i = tid; i < 72; i += 256) {
        float s = 0.f;
        #pragma unroll
        for (int w2 = 0; w2 < 8; w2++) s += red[w2][i];
        kvp[((size_t)(b * 16 + G) * 8 + chunk) * 72 + i] = s;
    }
}

// ------- o = normalize(relu(q)@kv), written as packed bf16 hi/lo pairs ------
// Also folds the kvp chunk-reduction (deterministic, done per-block in smem).
__global__ void __launch_bounds__(256)
o_kernel(const float* __restrict__ QKV,
         const float* __restrict__ D,
         const float* __restrict__ kvp,
         uint32_t* __restrict__ OH,
         uint32_t* __restrict__ OL)
{
    const int b = blockIdx.y;
    __shared__ float skv[16 * 72];
    for (int i = threadIdx.x; i < 16 * 72; i += 256) {
        float s = 0.f;
        #pragma unroll
        for (int c = 0; c < 8; c++)
            s += kvp[((size_t)(b * 16 + (i / 72)) * 8 + c) * 72 + (i % 72)];
        skv[i] = s;
    }
    __syncthreads();

    const int n = blockIdx.x * 256 + threadIdx.x;
    #pragma unroll
    for (int G = 0; G < 16; G++) {
        const float* base = (G < 8) ? QKV + ((size_t)b * CQKV + G * 24) * HW
                                    : D   + ((size_t)b * CQKV + (G - 8) * 24) * HW;
        float num[8] = {};
        float den = 0.f;
        #pragma unroll
        for (int d = 0; d < 8; d++) {
            float q = fmaxf(base[d * HW + n], 0.f);
            #pragma unroll
            for (int j = 0; j < 8; j++) num[j] += q * skv[G * 72 + d * 9 + j];
            den += q * skv[G * 72 + d * 9 + 8];
        }
        float inv = 1.f / (den + 1e-15f);
        #pragma unroll
        for (int jj = 0; jj < 4; jj++) {
            float v0 = num[2 * jj] * inv, v1 = num[2 * jj + 1] * inv;
            float h0, l0, h1, l1;
            bsplit(v0, h0, l0); bsplit(v1, h1, l1);
            size_t o = ((size_t)b * 64 + G * 4 + jj) * HW + n;
            OH[o] = bpack(h0, h1);
            OL[o] = bpack(l0, l1);
        }
    }
}

// ---------------- launch --------------------------------------------------
extern "C" void kernel_launch(void* const* d_in, const int* in_sizes, int n_in,
                              void* d_out, int out_size)
{
    const float* x     = (const float*)d_in[0];
    const float* W_qkv = (const float*)d_in[1];
    const float* W_p   = (const float*)d_in[2];
    const float* W_d   = (const float*)d_in[3];
    const float* W_ffn = (const float*)d_in[4];
    const float* gamma = (const float*)d_in[5];
    const float* beta  = (const float*)d_in[6];
    const float* mean  = (const float*)d_in[7];
    const float* var   = (const float*)d_in[8];
    float* out = (float*)d_out;

    float *qkv, *d, *kvp;
    uint32_t *xh, *xl, *oh, *ol, *wqh, *wql, *wfh, *wfl;
    cudaGetSymbolAddress((void**)&qkv, g_qkv);
    cudaGetSymbolAddress((void**)&d,   g_d);
    cudaGetSymbolAddress((void**)&xh,  g_xh);
    cudaGetSymbolAddress((void**)&xl,  g_xl);
    cudaGetSymbolAddress((void**)&oh,  g_oh);
    cudaGetSymbolAddress((void**)&ol,  g_ol);
    cudaGetSymbolAddress((void**)&wqh, g_wqh);
    cudaGetSymbolAddress((void**)&wql, g_wql);
    cudaGetSymbolAddress((void**)&wfh, g_wfh);
    cudaGetSymbolAddress((void**)&wfl, g_wfl);
    cudaGetSymbolAddress((void**)&kvp, g_kvp);

    const int SMEM = 2 * 9472 * 4;    // 75776 B
    cudaFuncSetAttribute(hgemm<256, 0>, cudaFuncAttributeMaxDynamicSharedMemorySize, SMEM);
    cudaFuncSetAttribute(hgemm<128, 1>, cudaFuncAttributeMaxDynamicSharedMemorySize, SMEM);

    // 0) operand conversions (once per call)
    wsplit_kernel<<<(256 * 128 + 255) / 256, 256>>>(W_qkv, wqh, wql, CQKV * 128, 256 * 128);
    wsplit_kernel<<<(256 * 64 + 255) / 256, 256>>>(W_ffn, wfh, wfl, 256 * 64, 256 * 64);
    xsplit_kernel<<<NB * 128 * (HW / 4) / 256, 256>>>(x, xh, xl);

    // 1) qkv = W_qkv @ x   (M padded to 256, valid 192)
    hgemm<256, 0><<<dim3(HW / 128, 2, NB), 128, SMEM>>>(
        wqh, wql, xh, xl, qkv, CQKV, nullptr, nullptr, nullptr, nullptr);

    // 2) d = depthwise3x3(blockdiag(W_p) @ qkv)
    pdw_kernel<<<dim3(WIDTH / 2, 24, NB), 256>>>(qkv, W_p, W_d, d);

    // 3) kv partial sums (chunk reduction folded into o_kernel)
    kv_kernel<<<dim3(8, 16, NB), 256>>>(qkv, d, kvp);

    // 4) o = normalize(relu(q) @ kv) -> packed bf16 hi/lo pairs
    o_kernel<<<dim3(HW / 256, NB), 256>>>(qkv, d, kvp, oh, ol);

    // 5) out = BN(W_ffn @ o)
    hgemm<128, 1><<<dim3(HW / 128, 2, NB), 128, SMEM>>>(
        wfh, wfl, oh, ol, out, 256, gamma, beta, mean, var);
}

// round 9
// speedup vs baseline: 1.5963x; 1.5963x over previous
#include <cuda_runtime.h>
#include <cuda_fp16.h>
#include <math.h>
#include <stdint.h>

#define HW    16384
#define WIDTH 128
#define NB    8
#define CQKV  192

// ---------------- scratch (static device allocations; no cudaMalloc) --------
__device__ float    g_qkv[NB * CQKV * HW];    // 100.7 MB
__device__ float    g_d  [NB * CQKV * HW];    // 100.7 MB
__device__ uint32_t g_xh [NB * 128 * HW];     // x packed fp16-pair (67 MB)
__device__ uint32_t g_oh [NB * 64 * HW];      // o packed fp16-pair (33.5 MB)
__device__ uint32_t g_wqh[CQKV * 128];        // qkv weights packed
__device__ uint32_t g_wfh[256 * 64];          // ffn weights packed
__device__ float    g_kvp[NB * 16 * 8 * 72];

// ---------------- fp16 helpers ----------------------------------------------
__device__ __forceinline__ uint32_t hpack(float a, float b) {
    __half2 t = __floats2half2_rn(a, b);      // .x = a (low), .y = b (high)
    return *reinterpret_cast<uint32_t*>(&t);
}
__device__ __forceinline__ void mma_fp16(float c[4], const uint32_t a[4], const uint32_t b[2]) {
    asm volatile(
        "mma.sync.aligned.m16n8k16.row.col.f32.f16.f16.f32 "
        "{%0,%1,%2,%3}, {%4,%5,%6,%7}, {%8,%9}, {%0,%1,%2,%3};\n"
        : "+f"(c[0]), "+f"(c[1]), "+f"(c[2]), "+f"(c[3])
        : "r"(a[0]), "r"(a[1]), "r"(a[2]), "r"(a[3]), "r"(b[0]), "r"(b[1]));
}
__device__ __forceinline__ uint32_t smem_u32(const void* p) {
    uint32_t a;
    asm("{ .reg .u64 t; cvta.to.shared.u64 t, %1; cvt.u32.u64 %0, t; }" : "=r"(a) : "l"(p));
    return a;
}
__device__ __forceinline__ void cpa16(uint32_t dst, const void* src) {
    asm volatile("cp.async.cg.shared.global [%0], [%1], 16;\n" :: "r"(dst), "l"(src));
}
#define CPA_COMMIT() asm volatile("cp.async.commit_group;\n" ::: "memory")
#define CPA_WAIT1()  asm volatile("cp.async.wait_group 1;\n" ::: "memory")
#define CPA_WAIT0()  asm volatile("cp.async.wait_group 0;\n" ::: "memory")

// ---------------- convert kernels -------------------------------------------
// W row-major MxK -> packed fp16 k-pair words
__global__ void wcvt_kernel(const float* __restrict__ W,
                            uint32_t* __restrict__ WH, int npairs)
{
    int i = blockIdx.x * 256 + threadIdx.x;
    if (i >= npairs) return;
    WH[i] = hpack(W[2 * i], W[2 * i + 1]);
}

// X [b][K][HW] -> packed fp16 k-pair array [b][K/2][HW]
__global__ void xcvt_kernel(const float* __restrict__ X, uint32_t* __restrict__ XH)
{
    int idx = blockIdx.x * 256 + threadIdx.x;
    int n  = (idx & 4095) * 4;
    int t  = idx >> 12;                           // b*128 + kp
    const float4 a = *(const float4*)&X[(size_t)t * 2 * HW + n];
    const float4 b = *(const float4*)&X[(size_t)t * 2 * HW + HW + n];
    uint4 w;
    w.x = hpack(a.x, b.x);
    w.y = hpack(a.y, b.y);
    w.z = hpack(a.z, b.z);
    w.w = hpack(a.w, b.w);
    *(uint4*)&XH[(size_t)t * HW + n] = w;
}

// ============ fp16 single-pass HMMA GEMM (R7 tile geometry) =================
// C[b](M x HW) = W(M x KTOT) * X[b](KTOT x HW)
// Block 64(M) x 64(N), 128 threads (4 warps, 32x32 warp tiles), k32 chunks,
// double-buffered cp.async stages. MODE 0: plain. MODE 1: batchnorm affine.
template <int KTOT, int MODE>
__global__ void __launch_bounds__(128)
hgemm(const uint32_t* __restrict__ AH,
      const uint32_t* __restrict__ BHg,
      float* __restrict__ C, int M,
      const float* __restrict__ gamma, const float* __restrict__ beta,
      const float* __restrict__ mean,  const float* __restrict__ var)
{
    constexpr int KP   = KTOT / 2;
    constexpr int NKIT = KTOT / 32;
    constexpr int SWRD = 2432;            // Ah[64][20]=1280 + Bh[16][72]=1152

    __shared__ uint32_t sm[2 * SWRD];     // 19456 B
    const uint32_t smb = smem_u32(sm);

    const int tid  = threadIdx.x;
    const int lane = tid & 31;
    const int warp = tid >> 5;
    const int wm   = warp >> 1;
    const int wn   = warp & 1;
    const int g    = lane >> 2;
    const int tg   = lane & 3;

    const int m0 = blockIdx.y * 64;
    const int n0 = blockIdx.x * 64;
    const uint32_t* Bh = BHg + (size_t)blockIdx.z * KP * HW;
    float*          Cb = C   + (size_t)blockIdx.z * M * HW;

    // loader roles
    const int arow = tid >> 1, aq = (tid & 1) * 8;   // A: 64 rows, 8-word halves
    const int brow = tid >> 3, bs = (tid & 7) * 8;   // B: 16 kp-rows, 8-word segs

    auto load_chunk = [&](int it, int stage) {
        const uint32_t s0 = smb + stage * SWRD * 4;
        const uint32_t* srcA = AH + (size_t)(m0 + arow) * KP + it * 16 + aq;
        uint32_t dA = s0 + (arow * 20 + aq) * 4;
        cpa16(dA,      srcA);
        cpa16(dA + 16, srcA + 4);
        const uint32_t* srcB = Bh + (size_t)(it * 16 + brow) * HW + n0 + bs;
        uint32_t dB = s0 + (1280 + brow * 72 + bs) * 4;
        cpa16(dB,      srcB);
        cpa16(dB + 16, srcB + 4);
    };

    load_chunk(0, 0);
    CPA_COMMIT();

    float c[2][4][4] = {};

    for (int it = 0; it < NKIT; it++) {
        if (it + 1 < NKIT) { load_chunk(it + 1, (it + 1) & 1); CPA_COMMIT(); CPA_WAIT1(); }
        else               { CPA_WAIT0(); }
        __syncthreads();

        const uint32_t* sAh = sm + (it & 1) * SWRD;
        const uint32_t* sBh = sAh + 1280;

        #pragma unroll
        for (int ks = 0; ks < 2; ks++) {
            const int kp0 = ks * 8;
            uint32_t ah[2][4], bh[4][2];
            #pragma unroll
            for (int mt = 0; mt < 2; mt++) {
                int r = wm * 32 + mt * 16 + g;
                ah[mt][0] = sAh[r * 20 + kp0 + tg];
                ah[mt][1] = sAh[(r + 8) * 20 + kp0 + tg];
                ah[mt][2] = sAh[r * 20 + kp0 + tg + 4];
                ah[mt][3] = sAh[(r + 8) * 20 + kp0 + tg + 4];
            }
            #pragma unroll
            for (int nt = 0; nt < 4; nt++) {
                int col = wn * 32 + nt * 8 + g;
                bh[nt][0] = sBh[(kp0 + tg) * 72 + col];
                bh[nt][1] = sBh[(kp0 + tg + 4) * 72 + col];
            }
            #pragma unroll
            for (int nt = 0; nt < 4; nt++)
                #pragma unroll
                for (int mt = 0; mt < 2; mt++) mma_fp16(c[mt][nt], ah[mt], bh[nt]);
        }
        __syncthreads();
    }

    // ---- epilogue: stage C tile in smem (stride 68), coalesced writeout ----
    float* Cs = (float*)sm;
    #pragma unroll
    for (int mt = 0; mt < 2; mt++)
        #pragma unroll
        for (int nt = 0; nt < 4; nt++) {
            int r   = wm * 32 + mt * 16 + g;
            int col = wn * 32 + nt * 8 + tg * 2;
            Cs[r * 68 + col]           = c[mt][nt][0];
            Cs[r * 68 + col + 1]       = c[mt][nt][1];
            Cs[(r + 8) * 68 + col]     = c[mt][nt][2];
            Cs[(r + 8) * 68 + col + 1] = c[mt][nt][3];
        }
    __syncthreads();

    #pragma unroll 8
    for (int i = tid; i < 4096; i += 128) {
        int r = i >> 6, n = i & 63;
        float v = Cs[r * 68 + n];
        if (MODE == 1) {
            int m = m0 + r;
            float sc = __ldg(&gamma[m]) * rsqrtf(__ldg(&var[m]) + 1e-5f);
            v = v * sc + __ldg(&beta[m]) - __ldg(&mean[m]) * sc;
        }
        Cb[(size_t)(m0 + r) * HW + n0 + n] = v;
    }
}

// ---------------- fused p-mix + depthwise 3x3 (SAME, cross-correlation) -----
__global__ void __launch_bounds__(256)
pdw_kernel(const float* __restrict__ QKV,
           const float* __restrict__ Wp,
           const float* __restrict__ Wd,
           float* __restrict__ D)
{
    __shared__ float sin[8][4][WIDTH];
    __shared__ float sp [8][4][WIDTH];

    const int b  = blockIdx.z;
    const int gr = blockIdx.y;
    const int h0 = blockIdx.x * 2;
    const int tid = threadIdx.x;
    const float* src = QKV + ((size_t)b * CQKV + gr * 8) * HW;

    #pragma unroll
    for (int i = 0; i < 16; i++) {
        int lin = tid + i * 256;
        int ch = lin >> 9, rs = (lin >> 7) & 3, col = lin & 127;
        int row = h0 - 1 + rs;
        sin[ch][rs][col] = ((unsigned)row < (unsigned)WIDTH)
                           ? src[ch * HW + row * WIDTH + col] : 0.f;
    }
    __syncthreads();

    #pragma unroll
    for (int i = 0; i < 16; i++) {
        int lin = tid + i * 256;
        int oc = lin >> 9, rs = (lin >> 7) & 3, col = lin & 127;
        float s = 0.f;
        #pragma unroll
        for (int ic = 0; ic < 8; ic++)
            s += __ldg(&Wp[gr * 64 + oc * 8 + ic]) * sin[ic][rs][col];
        sp[oc][rs][col] = s;
    }
    __syncthreads();

    #pragma unroll
    for (int i = 0; i < 8; i++) {
        int lin = tid + i * 256;
        int oc = lin >> 8, hr = (lin >> 7) & 1, col = lin & 127;
        int c = gr * 8 + oc;
        float s = 0.f;
        #pragma unroll
        for (int ky = 0; ky < 3; ky++) {
            float w0 = __ldg(&Wd[c * 9 + ky * 3 + 0]);
            float w1 = __ldg(&Wd[c * 9 + ky * 3 + 1]);
            float w2 = __ldg(&Wd[c * 9 + ky * 3 + 2]);
            const float* row = sp[oc][hr + ky];
            if (col > 0)   s += w0 * row[col - 1];
            s += w1 * row[col];
            if (col < 127) s += w2 * row[col + 1];
        }
        D[((size_t)b * CQKV + c) * HW + (h0 + hr) * WIDTH + col] = s;
    }
}

// ---------------- kv partial sums -------------------------------------------
__global__ void __launch_bounds__(256)
kv_kernel(const float* __restrict__ QKV,
          const float* __restrict__ D,
          float* __restrict__ kvp)
{
    const int b = blockIdx.z, G = blockIdx.y, chunk = blockIdx.x;
    const int tid = threadIdx.x;
    const float* base = (G < 8) ? QKV + ((size_t)b * CQKV + G * 24) * HW
                                : D   + ((size_t)b * CQKV + (G - 8) * 24) * HW;
    float acc[72];
    #pragma unroll
    for (int i = 0; i < 72; i++) acc[i] = 0.f;

    #pragma unroll
    for (int it = 0; it < 4; it++) {
        int n = chunk * 2048 + it * 512 + tid * 2;
        float2 kr[8], vr[8];
        #pragma unroll
        for (int d = 0; d < 8; d++) {
            float2 t = *(const float2*)&base[(8 + d) * HW + n];
            kr[d].x = fmaxf(t.x, 0.f); kr[d].y = fmaxf(t.y, 0.f);
        }
        #pragma unroll
        for (int e = 0; e < 8; e++) vr[e] = *(const float2*)&base[(16 + e) * HW + n];
        #pragma unroll
        for (int d = 0; d < 8; d++) {
            #pragma unroll
            for (int e = 0; e < 8; e++)
                acc[d * 9 + e] += kr[d].x * vr[e].x + kr[d].y * vr[e].y;
            acc[d * 9 + 8] += kr[d].x + kr[d].y;
        }
    }

    __shared__ float red[8][72];
    const int lane = tid & 31, warp = tid >> 5;
    #pragma unroll
    for (int i = 0; i < 72; i++) {
        float v = acc[i];
        #pragma unroll
        for (int off = 16; off; off >>= 1) v += __shfl_down_sync(0xffffffffu, v, off);
        if (lane == 0) red[warp][i] = v;
    }
    __syncthreads();
    for (int i = tid; i < 72; i += 256) {
        float s = 0.f;
        #pragma unroll
        for (int w2 = 0; w2 < 8; w2++) s += red[w2][i];
        kvp[((size_t)(b * 16 + G) * 8 + chunk) * 72 + i] = s;
    }
}

// ------- o = normalize(relu(q)@kv), written as packed fp16 pairs ------------
// Folds the kvp chunk-reduction (deterministic, per-block in smem).
__global__ void __launch_bounds__(256)
o_kernel(const float* __restrict__ QKV,
         const float* __restrict__ D,
         const float* __restrict__ kvp,
         uint32_t* __restrict__ OH)
{
    const int b = blockIdx.y;
    __shared__ float skv[16 * 72];
    for (int i = threadIdx.x; i < 16 * 72; i += 256) {
        float s = 0.f;
        #pragma unroll
        for (int c = 0; c < 8; c++)
            s += kvp[((size_t)(b * 16 + (i / 72)) * 8 + c) * 72 + (i % 72)];
        skv[i] = s;
    }
    __syncthreads();

    const int n = blockIdx.x * 256 + threadIdx.x;
    #pragma unroll
    for (int G = 0; G < 16; G++) {
        const float* base = (G < 8) ? QKV + ((size_t)b * CQKV + G * 24) * HW
                                    : D   + ((size_t)b * CQKV + (G - 8) * 24) * HW;
        float num[8] = {};
        float den = 0.f;
        #pragma unroll
        for (int d = 0; d < 8; d++) {
            float q = fmaxf(base[d * HW + n], 0.f);
            #pragma unroll
            for (int j = 0; j < 8; j++) num[j] += q * skv[G * 72 + d * 9 + j];
            den += q * skv[G * 72 + d * 9 + 8];
        }
        float inv = 1.f / (den + 1e-15f);
        #pragma unroll
        for (int jj = 0; jj < 4; jj++) {
            size_t o = ((size_t)b * 64 + G * 4 + jj) * HW + n;
            OH[o] = hpack(num[2 * jj] * inv, num[2 * jj + 1] * inv);
        }
    }
}

// ---------------- launch --------------------------------------------------
extern "C" void kernel_launch(void* const* d_in, const int* in_sizes, int n_in,
                              void* d_out, int out_size)
{
    const float* x     = (const float*)d_in[0];
    const float* W_qkv = (const float*)d_in[1];
    const float* W_p   = (const float*)d_in[2];
    const float* W_d   = (const float*)d_in[3];
    const float* W_ffn = (const float*)d_in[4];
    const float* gamma = (const float*)d_in[5];
    const float* beta  = (const float*)d_in[6];
    const float* mean  = (const float*)d_in[7];
    const float* var   = (const float*)d_in[8];
    float* out = (float*)d_out;

    float *qkv, *d, *kvp;
    uint32_t *xh, *oh, *wqh, *wfh;
    cudaGetSymbolAddress((void**)&qkv, g_qkv);
    cudaGetSymbolAddress((void**)&d,   g_d);
    cudaGetSymbolAddress((void**)&xh,  g_xh);
    cudaGetSymbolAddress((void**)&oh,  g_oh);
    cudaGetSymbolAddress((void**)&wqh, g_wqh);
    cudaGetSymbolAddress((void**)&wfh, g_wfh);
    cudaGetSymbolAddress((void**)&kvp, g_kvp);

    // 0) operand conversions (once per call)
    wcvt_kernel<<<(CQKV * 128 + 255) / 256, 256>>>(W_qkv, wqh, CQKV * 128);
    wcvt_kernel<<<(256 * 64 + 255) / 256, 256>>>(W_ffn, wfh, 256 * 64);
    xcvt_kernel<<<NB * 128 * (HW / 4) / 256, 256>>>(x, xh);

    // 1) qkv = W_qkv @ x   (fp16 single-pass HMMA)
    hgemm<256, 0><<<dim3(HW / 64, CQKV / 64, NB), 128>>>(
        wqh, xh, qkv, CQKV, nullptr, nullptr, nullptr, nullptr);

    // 2) d = depthwise3x3(blockdiag(W_p) @ qkv)
    pdw_kernel<<<dim3(WIDTH / 2, 24, NB), 256>>>(qkv, W_p, W_d, d);

    // 3) kv partial sums (chunk reduction folded into o_kernel)
    kv_kernel<<<dim3(8, 16, NB), 256>>>(qkv, d, kvp);

    // 4) o = normalize(relu(q) @ kv) -> packed fp16 pairs
    o_kernel<<<dim3(HW / 256, NB), 256>>>(qkv, d, kvp, oh);

    // 5) out = BN(W_ffn @ o)
    hgemm<128, 1><<<dim3(HW / 64, 256 / 64, NB), 128>>>(
        wfh, oh, out, 256, gamma, beta, mean, var);
}

// round 10
// speedup vs baseline: 1.6215x; 1.0158x over previous
#include <cuda_runtime.h>
#include <cuda_fp16.h>
#include <math.h>
#include <stdint.h>

#define HW    16384
#define WIDTH 128
#define NB    8
#define CQKV  192

// ---------------- scratch (static device allocations; no cudaMalloc) --------
__device__ float    g_qkv[NB * CQKV * HW];    // 100.7 MB
__device__ float    g_d  [NB * CQKV * HW];    // 100.7 MB
__device__ uint32_t g_xh [NB * 128 * HW];     // x packed fp16-pair (67 MB)
__device__ uint32_t g_oh [NB * 64 * HW];      // o packed fp16-pair (33.5 MB)
__device__ uint32_t g_wqh[CQKV * 128];        // qkv weights packed
__device__ uint32_t g_wfh[256 * 64];          // ffn weights packed
__device__ float    g_kvp[NB * 16 * 8 * 72];

// ---------------- fp16 helpers ----------------------------------------------
__device__ __forceinline__ uint32_t hpack(float a, float b) {
    __half2 t = __floats2half2_rn(a, b);      // .x = a (low), .y = b (high)
    return *reinterpret_cast<uint32_t*>(&t);
}
__device__ __forceinline__ void mma_fp16(float c[4], const uint32_t a[4], const uint32_t b[2]) {
    asm volatile(
        "mma.sync.aligned.m16n8k16.row.col.f32.f16.f16.f32 "
        "{%0,%1,%2,%3}, {%4,%5,%6,%7}, {%8,%9}, {%0,%1,%2,%3};\n"
        : "+f"(c[0]), "+f"(c[1]), "+f"(c[2]), "+f"(c[3])
        : "r"(a[0]), "r"(a[1]), "r"(a[2]), "r"(a[3]), "r"(b[0]), "r"(b[1]));
}
__device__ __forceinline__ uint32_t smem_u32(const void* p) {
    uint32_t a;
    asm("{ .reg .u64 t; cvta.to.shared.u64 t, %1; cvt.u32.u64 %0, t; }" : "=r"(a) : "l"(p));
    return a;
}
__device__ __forceinline__ void cpa16(uint32_t dst, const void* src) {
    asm volatile("cp.async.cg.shared.global [%0], [%1], 16;\n" :: "r"(dst), "l"(src));
}
#define CPA_COMMIT() asm volatile("cp.async.commit_group;\n" ::: "memory")
#define CPA_WAIT2()  asm volatile("cp.async.wait_group 2;\n" ::: "memory")
#define CPA_WAIT1()  asm volatile("cp.async.wait_group 1;\n" ::: "memory")
#define CPA_WAIT0()  asm volatile("cp.async.wait_group 0;\n" ::: "memory")

// ---------------- convert kernels -------------------------------------------
__global__ void wcvt_kernel(const float* __restrict__ W,
                            uint32_t* __restrict__ WH, int npairs)
{
    int i = blockIdx.x * 256 + threadIdx.x;
    if (i >= npairs) return;
    WH[i] = hpack(W[2 * i], W[2 * i + 1]);
}

// X [b][K][HW] -> packed fp16 k-pair array [b][K/2][HW]
__global__ void xcvt_kernel(const float* __restrict__ X, uint32_t* __restrict__ XH)
{
    int idx = blockIdx.x * 256 + threadIdx.x;
    int n  = (idx & 4095) * 4;
    int t  = idx >> 12;                           // b*128 + kp
    const float4 a = *(const float4*)&X[(size_t)t * 2 * HW + n];
    const float4 b = *(const float4*)&X[(size_t)t * 2 * HW + HW + n];
    uint4 w;
    w.x = hpack(a.x, b.x);
    w.y = hpack(a.y, b.y);
    w.z = hpack(a.z, b.z);
    w.w = hpack(a.w, b.w);
    *(uint4*)&XH[(size_t)t * HW + n] = w;
}

// ============ fp16 single-pass HMMA GEMM, 64x128 block, 32x64 warp tiles ====
// C[b](M x HW) = W(M x KTOT) * X[b](KTOT x HW)
// 128 threads = 4 warps (2x2), k32 chunks, 3-stage cp.async pipeline.
// MODE 0: plain store. MODE 1: batchnorm affine on channel (row).
template <int KTOT, int MODE>
__global__ void __launch_bounds__(128)
hgemm(const uint32_t* __restrict__ AH,
      const uint32_t* __restrict__ BHg,
      float* __restrict__ C, int M,
      const float* __restrict__ gamma, const float* __restrict__ beta,
      const float* __restrict__ mean,  const float* __restrict__ var)
{
    constexpr int KP   = KTOT / 2;
    constexpr int NKIT = KTOT / 32;
    constexpr int SWRD = 3456;            // A[64][20]=1280 + B[16][136]=2176
    constexpr int NSTG = 3;

    __shared__ uint32_t sm[NSTG * SWRD];  // 41472 B
    const uint32_t smb = smem_u32(sm);

    const int tid  = threadIdx.x;
    const int lane = tid & 31;
    const int warp = tid >> 5;
    const int wm   = warp >> 1;           // 0..1 -> 32 rows
    const int wn   = warp & 1;            // 0..1 -> 64 cols
    const int g    = lane >> 2;
    const int tg   = lane & 3;

    const int m0 = blockIdx.y * 64;
    const int n0 = blockIdx.x * 128;
    const uint32_t* Bh = BHg + (size_t)blockIdx.z * KP * HW;
    float*          Cb = C   + (size_t)blockIdx.z * M * HW;

    // loader roles
    const int arow = tid >> 1, aq = (tid & 1) * 8;    // A: 64 rows, 8-word halves
    const int brow = tid >> 3, bs = (tid & 7) * 16;   // B: 16 kp-rows, 16-word segs

    auto load_chunk = [&](int it, int stage) {
        const uint32_t s0 = smb + stage * SWRD * 4;
        const uint32_t* srcA = AH + (size_t)(m0 + arow) * KP + it * 16 + aq;
        uint32_t dA = s0 + (arow * 20 + aq) * 4;
        cpa16(dA,      srcA);
        cpa16(dA + 16, srcA + 4);
        const uint32_t* srcB = Bh + (size_t)(it * 16 + brow) * HW + n0 + bs;
        uint32_t dB = s0 + (1280 + brow * 136 + bs) * 4;
        #pragma unroll
        for (int q = 0; q < 4; q++) cpa16(dB + q * 16, srcB + q * 4);
    };

    load_chunk(0, 0); CPA_COMMIT();
    load_chunk(1, 1); CPA_COMMIT();

    float c[2][8][4] = {};

    for (int it = 0; it < NKIT; it++) {
        if (it + 2 < NKIT) { load_chunk(it + 2, (it + 2) % NSTG); CPA_COMMIT(); CPA_WAIT2(); }
        else if (it + 1 < NKIT) { CPA_WAIT1(); }
        else { CPA_WAIT0(); }
        __syncthreads();

        const uint32_t* sAh = sm + (it % NSTG) * SWRD;
        const uint32_t* sBh = sAh + 1280;

        #pragma unroll
        for (int ks = 0; ks < 2; ks++) {
            const int kp0 = ks * 8;
            uint32_t ah[2][4], bh[8][2];
            #pragma unroll
            for (int mt = 0; mt < 2; mt++) {
                int r = wm * 32 + mt * 16 + g;
                ah[mt][0] = sAh[r * 20 + kp0 + tg];
                ah[mt][1] = sAh[(r + 8) * 20 + kp0 + tg];
                ah[mt][2] = sAh[r * 20 + kp0 + tg + 4];
                ah[mt][3] = sAh[(r + 8) * 20 + kp0 + tg + 4];
            }
            #pragma unroll
            for (int nt = 0; nt < 8; nt++) {
                int col = wn * 64 + nt * 8 + g;
                bh[nt][0] = sBh[(kp0 + tg) * 136 + col];
                bh[nt][1] = sBh[(kp0 + tg + 4) * 136 + col];
            }
            #pragma unroll
            for (int nt = 0; nt < 8; nt++)
                #pragma unroll
                for (int mt = 0; mt < 2; mt++) mma_fp16(c[mt][nt], ah[mt], bh[nt]);
        }
        __syncthreads();
    }

    // ---- epilogue: stage C tile in smem (stride 132), coalesced writeout ----
    float* Cs = (float*)sm;               // 64*132 = 8448 w (fits in 10368)
    #pragma unroll
    for (int mt = 0; mt < 2; mt++)
        #pragma unroll
        for (int nt = 0; nt < 8; nt++) {
            int r   = wm * 32 + mt * 16 + g;
            int col = wn * 64 + nt * 8 + tg * 2;
            Cs[r * 132 + col]           = c[mt][nt][0];
            Cs[r * 132 + col + 1]       = c[mt][nt][1];
            Cs[(r + 8) * 132 + col]     = c[mt][nt][2];
            Cs[(r + 8) * 132 + col + 1] = c[mt][nt][3];
        }
    __syncthreads();

    #pragma unroll 8
    for (int i = tid; i < 8192; i += 128) {
        int r = i >> 7, n = i & 127;
        float v = Cs[r * 132 + n];
        if (MODE == 1) {
            int m = m0 + r;
            float sc = __ldg(&gamma[m]) * rsqrtf(__ldg(&var[m]) + 1e-5f);
            v = v * sc + __ldg(&beta[m]) - __ldg(&mean[m]) * sc;
        }
        Cb[(size_t)(m0 + r) * HW + n0 + n] = v;
    }
}

// ---------------- fused p-mix + depthwise 3x3 (SAME, cross-correlation) -----
__global__ void __launch_bounds__(256)
pdw_kernel(const float* __restrict__ QKV,
           const float* __restrict__ Wp,
           const float* __restrict__ Wd,
           float* __restrict__ D)
{
    __shared__ float sin[8][4][WIDTH];
    __shared__ float sp [8][4][WIDTH];

    const int b  = blockIdx.z;
    const int gr = blockIdx.y;
    const int h0 = blockIdx.x * 2;
    const int tid = threadIdx.x;
    const float* src = QKV + ((size_t)b * CQKV + gr * 8) * HW;

    #pragma unroll
    for (int i = 0; i < 16; i++) {
        int lin = tid + i * 256;
        int ch = lin >> 9, rs = (lin >> 7) & 3, col = lin & 127;
        int row = h0 - 1 + rs;
        sin[ch][rs][col] = ((unsigned)row < (unsigned)WIDTH)
                           ? src[ch * HW + row * WIDTH + col] : 0.f;
    }
    __syncthreads();

    #pragma unroll
    for (int i = 0; i < 16; i++) {
        int lin = tid + i * 256;
        int oc = lin >> 9, rs = (lin >> 7) & 3, col = lin & 127;
        float s = 0.f;
        #pragma unroll
        for (int ic = 0; ic < 8; ic++)
            s += __ldg(&Wp[gr * 64 + oc * 8 + ic]) * sin[ic][rs][col];
        sp[oc][rs][col] = s;
    }
    __syncthreads();

    #pragma unroll
    for (int i = 0; i < 8; i++) {
        int lin = tid + i * 256;
        int oc = lin >> 8, hr = (lin >> 7) & 1, col = lin & 127;
        int c = gr * 8 + oc;
        float s = 0.f;
        #pragma unroll
        for (int ky = 0; ky < 3; ky++) {
            float w0 = __ldg(&Wd[c * 9 + ky * 3 + 0]);
            float w1 = __ldg(&Wd[c * 9 + ky * 3 + 1]);
            float w2 = __ldg(&Wd[c * 9 + ky * 3 + 2]);
            const float* row = sp[oc][hr + ky];
            if (col > 0)   s += w0 * row[col - 1];
            s += w1 * row[col];
            if (col < 127) s += w2 * row[col + 1];
        }
        D[((size_t)b * CQKV + c) * HW + (h0 + hr) * WIDTH + col] = s;
    }
}

// ---------------- kv partial sums -------------------------------------------
__global__ void __launch_bounds__(256)
kv_kernel(const float* __restrict__ QKV,
          const float* __restrict__ D,
          float* __restrict__ kvp)
{
    const int b = blockIdx.z, G = blockIdx.y, chunk = blockIdx.x;
    const int tid = threadIdx.x;
    const float* base = (G < 8) ? QKV + ((size_t)b * CQKV + G * 24) * HW
                                : D   + ((size_t)b * CQKV + (G - 8) * 24) * HW;
    float acc[72];
    #pragma unroll
    for (int i = 0; i < 72; i++) acc[i] = 0.f;

    #pragma unroll
    for (int it = 0; it < 4; it++) {
        int n = chunk * 2048 + it * 512 + tid * 2;
        float2 kr[8], vr[8];
        #pragma unroll
        for (int d = 0; d < 8; d++) {
            float2 t = *(const float2*)&base[(8 + d) * HW + n];
            kr[d].x = fmaxf(t.x, 0.f); kr[d].y = fmaxf(t.y, 0.f);
        }
        #pragma unroll
        for (int e = 0; e < 8; e++) vr[e] = *(const float2*)&base[(16 + e) * HW + n];
        #pragma unroll
        for (int d = 0; d < 8; d++) {
            #pragma unroll
            for (int e = 0; e < 8; e++)
                acc[d * 9 + e] += kr[d].x * vr[e].x + kr[d].y * vr[e].y;
            acc[d * 9 + 8] += kr[d].x + kr[d].y;
        }
    }

    __shared__ float red[8][72];
    const int lane = tid & 31, warp = tid >> 5;
    #pragma unroll
    for (int i = 0; i < 72; i++) {
        float v = acc[i];
        #pragma unroll
        for (int off = 16; off; off >>= 1) v += __shfl_down_sync(0xffffffffu, v, off);
        if (lane == 0) red[warp][i] = v;
    }
    __syncthreads();
    for (int i = tid; i < 72; i += 256) {
        float s = 0.f;
        #pragma unroll
        for (int w2 = 0; w2 < 8; w2++) s += red[w2][i];
        kvp[((size_t)(b * 16 + G) * 8 + chunk) * 72 + i] = s;
    }
}

// ------- o = normalize(relu(q)@kv), written as packed fp16 pairs ------------
__global__ void __launch_bounds__(256)
o_kernel(const float* __restrict__ QKV,
         const float* __restrict__ D,
         const float* __restrict__ kvp,
         uint32_t* __restrict__ OH)
{
    const int b = blockIdx.y;
    __shared__ float skv[16 * 72];
    for (int i = threadIdx.x; i < 16 * 72; i += 256) {
        float s = 0.f;
        #pragma unroll
        for (int c = 0; c < 8; c++)
            s += kvp[((size_t)(b * 16 + (i / 72)) * 8 + c) * 72 + (i % 72)];
        skv[i] = s;
    }
    __syncthreads();

    const int n = blockIdx.x * 256 + threadIdx.x;
    #pragma unroll
    for (int G = 0; G < 16; G++) {
        const float* base = (G < 8) ? QKV + ((size_t)b * CQKV + G * 24) * HW
                                    : D   + ((size_t)b * CQKV + (G - 8) * 24) * HW;
        float num[8] = {};
        float den = 0.f;
        #pragma unroll
        for (int d = 0; d < 8; d++) {
            float q = fmaxf(base[d * HW + n], 0.f);
            #pragma unroll
            for (int j = 0; j < 8; j++) num[j] += q * skv[G * 72 + d * 9 + j];
            den += q * skv[G * 72 + d * 9 + 8];
        }
        float inv = 1.f / (den + 1e-15f);
        #pragma unroll
        for (int jj = 0; jj < 4; jj++) {
            size_t o = ((size_t)b * 64 + G * 4 + jj) * HW + n;
            OH[o] = hpack(num[2 * jj] * inv, num[2 * jj + 1] * inv);
        }
    }
}

// ---------------- launch --------------------------------------------------
extern "C" void kernel_launch(void* const* d_in, const int* in_sizes, int n_in,
                              void* d_out, int out_size)
{
    const float* x     = (const float*)d_in[0];
    const float* W_qkv = (const float*)d_in[1];
    const float* W_p   = (const float*)d_in[2];
    const float* W_d   = (const float*)d_in[3];
    const float* W_ffn = (const float*)d_in[4];
    const float* gamma = (const float*)d_in[5];
    const float* beta  = (const float*)d_in[6];
    const float* mean  = (const float*)d_in[7];
    const float* var   = (const float*)d_in[8];
    float* out = (float*)d_out;

    float *qkv, *d, *kvp;
    uint32_t *xh, *oh, *wqh, *wfh;
    cudaGetSymbolAddress((void**)&qkv, g_qkv);
    cudaGetSymbolAddress((void**)&d,   g_d);
    cudaGetSymbolAddress((void**)&xh,  g_xh);
    cudaGetSymbolAddress((void**)&oh,  g_oh);
    cudaGetSymbolAddress((void**)&wqh, g_wqh);
    cudaGetSymbolAddress((void**)&wfh, g_wfh);
    cudaGetSymbolAddress((void**)&kvp, g_kvp);

    // 0) operand conversions (once per call)
    wcvt_kernel<<<(CQKV * 128 + 255) / 256, 256>>>(W_qkv, wqh, CQKV * 128);
    wcvt_kernel<<<(256 * 64 + 255) / 256, 256>>>(W_ffn, wfh, 256 * 64);
    xcvt_kernel<<<NB * 128 * (HW / 4) / 256, 256>>>(x, xh);

    // 1) qkv = W_qkv @ x   (fp16 HMMA, 64x128 block, 3-stage pipeline)
    hgemm<256, 0><<<dim3(HW / 128, CQKV / 64, NB), 128>>>(
        wqh, xh, qkv, CQKV, nullptr, nullptr, nullptr, nullptr);

    // 2) d = depthwise3x3(blockdiag(W_p) @ qkv)
    pdw_kernel<<<dim3(WIDTH / 2, 24, NB), 256>>>(qkv, W_p, W_d, d);

    // 3) kv partial sums (chunk reduction folded into o_kernel)
    kv_kernel<<<dim3(8, 16, NB), 256>>>(qkv, d, kvp);

    // 4) o = normalize(relu(q) @ kv) -> packed fp16 pairs
    o_kernel<<<dim3(HW / 256, NB), 256>>>(qkv, d, kvp, oh);

    // 5) out = BN(W_ffn @ o)
    hgemm<128, 1><<<dim3(HW / 128, 256 / 64, NB), 128>>>(
        wfh, oh, out, 256, gamma, beta, mean, var);
}

// round 12
// speedup vs baseline: 1.6476x; 1.0161x over previous
#include <cuda_runtime.h>
#include <cuda_fp16.h>
#include <math.h>
#include <stdint.h>

#define HW    16384
#define WIDTH 128
#define NB    8
#define CQKV  192

// ---------------- scratch (static device allocations; no cudaMalloc) --------
__device__ float    g_qkv[NB * CQKV * HW];    // 100.7 MB
__device__ float    g_d  [NB * CQKV * HW];    // 100.7 MB
__device__ uint32_t g_xh [NB * 128 * HW];     // x packed fp16-pair (67 MB)
__device__ uint32_t g_oh [NB * 64 * HW];      // o packed fp16-pair (33.5 MB)
__device__ uint32_t g_wqh[CQKV * 128];        // qkv weights packed
__device__ uint32_t g_wfh[256 * 64];          // ffn weights packed
__device__ float    g_kvp[NB * 16 * 8 * 72];

// ---------------- fp16 helpers ----------------------------------------------
__device__ __forceinline__ uint32_t hpack(float a, float b) {
    __half2 t = __floats2half2_rn(a, b);      // .x = a (low), .y = b (high)
    return *reinterpret_cast<uint32_t*>(&t);
}
__device__ __forceinline__ void mma_fp16(float c[4], const uint32_t a[4], const uint32_t b[2]) {
    asm volatile(
        "mma.sync.aligned.m16n8k16.row.col.f32.f16.f16.f32 "
        "{%0,%1,%2,%3}, {%4,%5,%6,%7}, {%8,%9}, {%0,%1,%2,%3};\n"
        : "+f"(c[0]), "+f"(c[1]), "+f"(c[2]), "+f"(c[3])
        : "r"(a[0]), "r"(a[1]), "r"(a[2]), "r"(a[3]), "r"(b[0]), "r"(b[1]));
}
__device__ __forceinline__ uint32_t smem_u32(const void* p) {
    uint32_t a;
    asm("{ .reg .u64 t; cvta.to.shared.u64 t, %1; cvt.u32.u64 %0, t; }" : "=r"(a) : "l"(p));
    return a;
}
__device__ __forceinline__ void cpa16(uint32_t dst, const void* src) {
    asm volatile("cp.async.cg.shared.global [%0], [%1], 16;\n" :: "r"(dst), "l"(src));
}
#define CPA_COMMIT() asm volatile("cp.async.commit_group;\n" ::: "memory")
#define CPA_WAIT2()  asm volatile("cp.async.wait_group 2;\n" ::: "memory")
#define CPA_WAIT1()  asm volatile("cp.async.wait_group 1;\n" ::: "memory")
#define CPA_WAIT0()  asm volatile("cp.async.wait_group 0;\n" ::: "memory")

// ---------------- convert kernels -------------------------------------------
__global__ void wcvt_kernel(const float* __restrict__ W,
                            uint32_t* __restrict__ WH, int npairs)
{
    int i = blockIdx.x * 256 + threadIdx.x;
    if (i >= npairs) return;
    WH[i] = hpack(W[2 * i], W[2 * i + 1]);
}

// X [b][K][HW] -> packed fp16 k-pair array [b][K/2][HW]
__global__ void xcvt_kernel(const float* __restrict__ X, uint32_t* __restrict__ XH)
{
    int idx = blockIdx.x * 256 + threadIdx.x;
    int n  = (idx & 4095) * 4;
    int t  = idx >> 12;                           // b*128 + kp
    const float4 a = *(const float4*)&X[(size_t)t * 2 * HW + n];
    const float4 b = *(const float4*)&X[(size_t)t * 2 * HW + HW + n];
    uint4 w;
    w.x = hpack(a.x, b.x);
    w.y = hpack(a.y, b.y);
    w.z = hpack(a.z, b.z);
    w.w = hpack(a.w, b.w);
    *(uint4*)&XH[(size_t)t * HW + n] = w;
}

// ====== fp16 single-pass HMMA GEMM, TALL block: MROWS x 64, 32x64 warp tiles
// C[b](MROWS x HW) = W(MROWS x KTOT) * X[b](KTOT x HW)
// MROWS threads = MROWS/32 warps (each one 32-row band, all share B fragments),
// k32 chunks, 3-stage cp.async pipeline (lookahead 2). B read ONCE per (n0,b).
// MODE 0: plain store. MODE 1: batchnorm affine on channel (row).
template <int MROWS, int KTOT, int MODE>
__global__ void __launch_bounds__(MROWS)
hgemm_tall(const uint32_t* __restrict__ AH,
           const uint32_t* __restrict__ BHg,
           float* __restrict__ C,
           const float* __restrict__ gamma, const float* __restrict__ beta,
           const float* __restrict__ mean,  const float* __restrict__ var)
{
    constexpr int KP    = KTOT / 2;
    constexpr int NKIT  = KTOT / 32;
    constexpr int ABASE = MROWS * 20;             // A words per stage
    constexpr int SWRD  = ABASE + 16 * 72;        // + B words per stage
    constexpr int NSTG  = 3;

    extern __shared__ uint32_t sm[];
    const uint32_t smb = smem_u32(sm);

    const int tid  = threadIdx.x;
    const int lane = tid & 31;
    const int warp = tid >> 5;                    // 0..MROWS/32-1, M band
    const int g    = lane >> 2;
    const int tg   = lane & 3;

    const int n0 = blockIdx.x * 64;
    const uint32_t* Bh = BHg + (size_t)blockIdx.z * KP * HW;
    float*          Cb = C   + (size_t)blockIdx.z * MROWS * HW;

    auto load_chunk = [&](int it, int stage) {
        const uint32_t s0 = smb + (uint32_t)stage * SWRD * 4;
        // A: MROWS rows x 16 words; thread owns its row (4 cp.async of 16B)
        const uint32_t* srcA = AH + (size_t)tid * KP + it * 16;
        uint32_t dA = s0 + (uint32_t)(tid * 20) * 4;
        #pragma unroll
        for (int q = 0; q < 4; q++) cpa16(dA + q * 16, srcA + q * 4);
        // B: 16 kp-rows x 64 words = 256 chunks of 4 words
        if (tid < 256) {
            int row = tid >> 4, seg = (tid & 15) * 4;
            cpa16(s0 + (uint32_t)(ABASE + row * 72 + seg) * 4,
                  Bh + (size_t)(it * 16 + row) * HW + n0 + seg);
        }
        if (MROWS == 192 && tid < 64) {
            int c = 192 + tid;
            int row = c >> 4, seg = (c & 15) * 4;
            cpa16(s0 + (uint32_t)(ABASE + row * 72 + seg) * 4,
                  Bh + (size_t)(it * 16 + row) * HW + n0 + seg);
        }
    };

    load_chunk(0, 0); CPA_COMMIT();
    load_chunk(1, 1); CPA_COMMIT();

    float c[2][8][4] = {};

    for (int it = 0; it < NKIT; it++) {
        if (it + 2 < NKIT) { load_chunk(it + 2, (it + 2) % NSTG); CPA_COMMIT(); CPA_WAIT2(); }
        else if (it + 1 < NKIT) { CPA_WAIT1(); }
        else { CPA_WAIT0(); }
        __syncthreads();

        const uint32_t* sAh = sm + (it % NSTG) * SWRD;
        const uint32_t* sBh = sAh + ABASE;

        #pragma unroll
        for (int ks = 0; ks < 2; ks++) {
            const int kp0 = ks * 8;
            uint32_t ah[2][4], bh[8][2];
            #pragma unroll
            for (int mt = 0; mt < 2; mt++) {
                int r = warp * 32 + mt * 16 + g;
                ah[mt][0] = sAh[r * 20 + kp0 + tg];
                ah[mt][1] = sAh[(r + 8) * 20 + kp0 + tg];
                ah[mt][2] = sAh[r * 20 + kp0 + tg + 4];
                ah[mt][3] = sAh[(r + 8) * 20 + kp0 + tg + 4];
            }
            #pragma unroll
            for (int nt = 0; nt < 8; nt++) {
                int col = nt * 8 + g;
                bh[nt][0] = sBh[(kp0 + tg) * 72 + col];
                bh[nt][1] = sBh[(kp0 + tg + 4) * 72 + col];
            }
            #pragma unroll
            for (int nt = 0; nt < 8; nt++)
                #pragma unroll
                for (int mt = 0; mt < 2; mt++) mma_fp16(c[mt][nt], ah[mt], bh[nt]);
        }
        __syncthreads();
    }

    // ---- epilogue: stage C tile in smem (stride 68), coalesced writeout ----
    float* Cs = (float*)sm;
    #pragma unroll
    for (int mt = 0; mt < 2; mt++)
        #pragma unroll
        for (int nt = 0; nt < 8; nt++) {
            int r   = warp * 32 + mt * 16 + g;
            int col = nt * 8 + tg * 2;
            Cs[r * 68 + col]           = c[mt][nt][0];
            Cs[r * 68 + col + 1]       = c[mt][nt][1];
            Cs[(r + 8) * 68 + col]     = c[mt][nt][2];
            Cs[(r + 8) * 68 + col + 1] = c[mt][nt][3];
        }
    __syncthreads();

    #pragma unroll 8
    for (int i = tid; i < MROWS * 64; i += MROWS) {
        int r = i >> 6, n = i & 63;
        float v = Cs[r * 68 + n];
        if (MODE == 1) {
            float sc = __ldg(&gamma[r]) * rsqrtf(__ldg(&var[r]) + 1e-5f);
            v = v * sc + __ldg(&beta[r]) - __ldg(&mean[r]) * sc;
        }
        Cb[(size_t)r * HW + n0 + n] = v;
    }
}

// ------- fused p-mix + depthwise 3x3 (SAME), 4 output rows per block --------
__global__ void __launch_bounds__(256)
pdw_kernel(const float* __restrict__ QKV,
           const float* __restrict__ Wp,
           const float* __restrict__ Wd,
           float* __restrict__ D)
{
    __shared__ float sin[8][6][WIDTH];    // 24 KB
    __shared__ float sp [8][6][WIDTH];    // 24 KB

    const int b  = blockIdx.z;
    const int gr = blockIdx.y;
    const int h0 = blockIdx.x * 4;        // output rows h0..h0+3
    const int tid = threadIdx.x;
    const float* src = QKV + ((size_t)b * CQKV + gr * 8) * HW;

    // load 8 in-channels x 6 rows (h0-1 .. h0+4, zero-padded)
    #pragma unroll
    for (int i = 0; i < 24; i++) {
        int lin = tid + i * 256;          // 0..6143
        int ch = lin / 768, rem = lin - ch * 768;
        int rs = rem >> 7, col = rem & 127;
        int row = h0 - 1 + rs;
        sin[ch][rs][col] = ((unsigned)row < (unsigned)WIDTH)
                           ? src[ch * HW + row * WIDTH + col] : 0.f;
    }
    __syncthreads();

    // mix: p[o][r][c] = sum_i Wp[gr][o][i] * in[i][r][c]
    #pragma unroll
    for (int i = 0; i < 24; i++) {
        int lin = tid + i * 256;
        int oc = lin / 768, rem = lin - oc * 768;
        int rs = rem >> 7, col = rem & 127;
        float s = 0.f;
        #pragma unroll
        for (int ic = 0; ic < 8; ic++)
            s += __ldg(&Wp[gr * 64 + oc * 8 + ic]) * sin[ic][rs][col];
        sp[oc][rs][col] = s;
    }
    __syncthreads();

    // conv: out[oc][h0+hr][col], taps from sp rows hr..hr+2
    #pragma unroll
    for (int i = 0; i < 16; i++) {
        int lin = tid + i * 256;          // 0..4095
        int oc = lin >> 9, hr = (lin >> 7) & 3, col = lin & 127;
        int c = gr * 8 + oc;
        float s = 0.f;
        #pragma unroll
        for (int ky = 0; ky < 3; ky++) {
            float w0 = __ldg(&Wd[c * 9 + ky * 3 + 0]);
            float w1 = __ldg(&Wd[c * 9 + ky * 3 + 1]);
            float w2 = __ldg(&Wd[c * 9 + ky * 3 + 2]);
            const float* row = sp[oc][hr + ky];
            if (col > 0)   s += w0 * row[col - 1];
            s += w1 * row[col];
            if (col < 127) s += w2 * row[col + 1];
        }
        D[((size_t)b * CQKV + c) * HW + (h0 + hr) * WIDTH + col] = s;
    }
}

// ---------------- kv partial sums -------------------------------------------
__global__ void __launch_bounds__(256)
kv_kernel(const float* __restrict__ QKV,
          const float* __restrict__ D,
          float* __restrict__ kvp)
{
    const int b = blockIdx.z, G = blockIdx.y, chunk = blockIdx.x;
    const int tid = threadIdx.x;
    const float* base = (G < 8) ? QKV + ((size_t)b * CQKV + G * 24) * HW
                                : D   + ((size_t)b * CQKV + (G - 8) * 24) * HW;
    float acc[72];
    #pragma unroll
    for (int i = 0; i < 72; i++) acc[i] = 0.f;

    #pragma unroll
    for (int it = 0; it < 4; it++) {
        int n = chunk * 2048 + it * 512 + tid * 2;
        float2 kr[8], vr[8];
        #pragma unroll
        for (int d = 0; d < 8; d++) {
            float2 t = *(const float2*)&base[(8 + d) * HW + n];
            kr[d].x = fmaxf(t.x, 0.f); kr[d].y = fmaxf(t.y, 0.f);
        }
        #pragma unroll
        for (int e = 0; e < 8; e++) vr[e] = *(const float2*)&base[(16 + e) * HW + n];
        #pragma unroll
        for (int d = 0; d < 8; d++) {
            #pragma unroll
            for (int e = 0; e < 8; e++)
                acc[d * 9 + e] += kr[d].x * vr[e].x + kr[d].y * vr[e].y;
            acc[d * 9 + 8] += kr[d].x + kr[d].y;
        }
    }

    __shared__ float red[8][72];
    const int lane = tid & 31, warp = tid >> 5;
    #pragma unroll
    for (int i = 0; i < 72; i++) {
        float v = acc[i];
        #pragma unroll
        for (int off = 16; off; off >>= 1) v += __shfl_down_sync(0xffffffffu, v, off);
        if (lane == 0) red[warp][i] = v;
    }
    __syncthreads();
    for (int i = tid; i < 72; i += 256) {
        float s = 0.f;
        #pragma unroll
        for (int w2 = 0; w2 < 8; w2++) s += red[w2][i];
        kvp[((size_t)(b * 16 + G) * 8 + chunk) * 72 + i] = s;
    }
}

// ------- o = normalize(relu(q)@kv), written as packed fp16 pairs ------------
__global__ void __launch_bounds__(256)
o_kernel(const float* __restrict__ QKV,
         const float* __restrict__ D,
         const float* __restrict__ kvp,
         uint32_t* __restrict__ OH)
{
    const int b = blockIdx.y;
    __shared__ float skv[16 * 72];
    for (int i = threadIdx.x; i < 16 * 72; i += 256) {
        float s = 0.f;
        #pragma unroll
        for (int c = 0; c < 8; c++)
            s += kvp[((size_t)(b * 16 + (i / 72)) * 8 + c) * 72 + (i % 72)];
        skv[i] = s;
    }
    __syncthreads();

    const int n = blockIdx.x * 256 + threadIdx.x;
    #pragma unroll
    for (int G = 0; G < 16; G++) {
        const float* base = (G < 8) ? QKV + ((size_t)b * CQKV + G * 24) * HW
                                    : D   + ((size_t)b * CQKV + (G - 8) * 24) * HW;
        float num[8] = {};
        float den = 0.f;
        #pragma unroll
        for (int d = 0; d < 8; d++) {
            float q = fmaxf(base[d * HW + n], 0.f);
            #pragma unroll
            for (int j = 0; j < 8; j++) num[j] += q * skv[G * 72 + d * 9 + j];
            den += q * skv[G * 72 + d * 9 + 8];
        }
        float inv = 1.f / (den + 1e-15f);
        #pragma unroll
        for (int jj = 0; jj < 4; jj++) {
            size_t o = ((size_t)b * 64 + G * 4 + jj) * HW + n;
            OH[o] = hpack(num[2 * jj] * inv, num[2 * jj + 1] * inv);
        }
    }
}

// ---------------- launch --------------------------------------------------
extern "C" void kernel_launch(void* const* d_in, const int* in_sizes, int n_in,
                              void* d_out, int out_size)
{
    const float* x     = (const float*)d_in[0];
    const float* W_qkv = (const float*)d_in[1];
    const float* W_p   = (const float*)d_in[2];
    const float* W_d   = (const float*)d_in[3];
    const float* W_ffn = (const float*)d_in[4];
    const float* gamma = (const float*)d_in[5];
    const float* beta  = (const float*)d_in[6];
    const float* mean  = (const float*)d_in[7];
    const float* var   = (const float*)d_in[8];
    float* out = (float*)d_out;

    float *qkv, *d, *kvp;
    uint32_t *xh, *oh, *wqh, *wfh;
    cudaGetSymbolAddress((void**)&qkv, g_qkv);
    cudaGetSymbolAddress((void**)&d,   g_d);
    cudaGetSymbolAddress((void**)&xh,  g_xh);
    cudaGetSymbolAddress((void**)&oh,  g_oh);
    cudaGetSymbolAddress((void**)&wqh, g_wqh);
    cudaGetSymbolAddress((void**)&wfh, g_wfh);
    cudaGetSymbolAddress((void**)&kvp, g_kvp);

    // dynamic smem: max(3*stage, epilogue staging)
    const int STG_QKV = 192 * 20 + 16 * 72;        // 4992 words
    const int STG_FFN = 256 * 20 + 16 * 72;        // 6272 words
    const int SM_QKV = ((3 * STG_QKV > 192 * 68) ? 3 * STG_QKV : 192 * 68) * 4;
    const int SM_FFN = ((3 * STG_FFN > 256 * 68) ? 3 * STG_FFN : 256 * 68) * 4;
    cudaFuncSetAttribute((const void*)hgemm_tall<192, 256, 0>,
                         cudaFuncAttributeMaxDynamicSharedMemorySize, SM_QKV);
    cudaFuncSetAttribute((const void*)hgemm_tall<256, 128, 1>,
                         cudaFuncAttributeMaxDynamicSharedMemorySize, SM_FFN);

    // 0) operand conversions (once per call)
    wcvt_kernel<<<(CQKV * 128 + 255) / 256, 256>>>(W_qkv, wqh, CQKV * 128);
    wcvt_kernel<<<(256 * 64 + 255) / 256, 256>>>(W_ffn, wfh, 256 * 64);
    xcvt_kernel<<<NB * 128 * (HW / 4) / 256, 256>>>(x, xh);

    // 1) qkv = W_qkv @ x   (tall fp16 HMMA: M=192 in one block-column)
    hgemm_tall<192, 256, 0><<<dim3(HW / 64, 1, NB), 192, SM_QKV>>>(
        wqh, xh, qkv, nullptr, nullptr, nullptr, nullptr);

    // 2) d = depthwise3x3(blockdiag(W_p) @ qkv)   (4-row strips)
    pdw_kernel<<<dim3(WIDTH / 4, 24, NB), 256>>>(qkv, W_p, W_d, d);

    // 3) kv partial sums (chunk reduction folded into o_kernel)
    kv_kernel<<<dim3(8, 16, NB), 256>>>(qkv, d, kvp);

    // 4) o = normalize(relu(q) @ kv) -> packed fp16 pairs
    o_kernel<<<dim3(HW / 256, NB), 256>>>(qkv, d, kvp, oh);

    // 5) out = BN(W_ffn @ o)   (tall fp16 HMMA: M=256 in one block-column)
    hgemm_tall<256, 128, 1><<<dim3(HW / 64, 1, NB), 256, SM_FFN>>>(
        wfh, oh, out, gamma, beta, mean, var);
}

// round 13
// speedup vs baseline: 1.8005x; 1.0928x over previous
#include <cuda_runtime.h>
#include <cuda_fp16.h>
#include <math.h>
#include <stdint.h>

#define HW    16384
#define WIDTH 128
#define NB    8
#define CQKV  192

// ---------------- scratch (static device allocations; no cudaMalloc) --------
__device__ float    g_qkv[NB * CQKV * HW];    // 100.7 MB
__device__ float    g_d  [NB * CQKV * HW];    // 100.7 MB
__device__ uint32_t g_xh [NB * 128 * HW];     // x packed fp16-pair (67 MB)
__device__ uint32_t g_oh [NB * 64 * HW];      // o packed fp16-pair (33.5 MB)
__device__ uint32_t g_wqh[CQKV * 128];        // qkv weights packed
__device__ uint32_t g_wfh[256 * 64];          // ffn weights packed
__device__ float    g_kvp[NB * 16 * 8 * 72];

// ---------------- fp16 helpers ----------------------------------------------
__device__ __forceinline__ uint32_t hpack(float a, float b) {
    __half2 t = __floats2half2_rn(a, b);      // .x = a (low), .y = b (high)
    return *reinterpret_cast<uint32_t*>(&t);
}
__device__ __forceinline__ void mma_fp16(float c[4], const uint32_t a[4], const uint32_t b[2]) {
    asm volatile(
        "mma.sync.aligned.m16n8k16.row.col.f32.f16.f16.f32 "
        "{%0,%1,%2,%3}, {%4,%5,%6,%7}, {%8,%9}, {%0,%1,%2,%3};\n"
        : "+f"(c[0]), "+f"(c[1]), "+f"(c[2]), "+f"(c[3])
        : "r"(a[0]), "r"(a[1]), "r"(a[2]), "r"(a[3]), "r"(b[0]), "r"(b[1]));
}
__device__ __forceinline__ uint32_t smem_u32(const void* p) {
    uint32_t a;
    asm("{ .reg .u64 t; cvta.to.shared.u64 t, %1; cvt.u32.u64 %0, t; }" : "=r"(a) : "l"(p));
    return a;
}
__device__ __forceinline__ void cpa16(uint32_t dst, const void* src) {
    asm volatile("cp.async.cg.shared.global [%0], [%1], 16;\n" :: "r"(dst), "l"(src));
}
#define CPA_COMMIT() asm volatile("cp.async.commit_group;\n" ::: "memory")
#define CPA_WAIT2()  asm volatile("cp.async.wait_group 2;\n" ::: "memory")
#define CPA_WAIT1()  asm volatile("cp.async.wait_group 1;\n" ::: "memory")
#define CPA_WAIT0()  asm volatile("cp.async.wait_group 0;\n" ::: "memory")

// ---------------- convert kernels -------------------------------------------
__global__ void wcvt_kernel(const float* __restrict__ W,
                            uint32_t* __restrict__ WH, int npairs)
{
    int i = blockIdx.x * 256 + threadIdx.x;
    if (i >= npairs) return;
    WH[i] = hpack(W[2 * i], W[2 * i + 1]);
}

// X [b][K][HW] -> packed fp16 k-pair array [b][K/2][HW]
__global__ void xcvt_kernel(const float* __restrict__ X, uint32_t* __restrict__ XH)
{
    int idx = blockIdx.x * 256 + threadIdx.x;
    int n  = (idx & 4095) * 4;
    int t  = idx >> 12;                           // b*128 + kp
    const float4 a = *(const float4*)&X[(size_t)t * 2 * HW + n];
    const float4 b = *(const float4*)&X[(size_t)t * 2 * HW + HW + n];
    uint4 w;
    w.x = hpack(a.x, b.x);
    w.y = hpack(a.y, b.y);
    w.z = hpack(a.z, b.z);
    w.w = hpack(a.w, b.w);
    *(uint4*)&XH[(size_t)t * HW + n] = w;
}

// ============ fp16 single-pass HMMA GEMM, 64x128 block, 32x64 warp tiles ====
// C[b](M x HW) = W(M x KTOT) * X[b](KTOT x HW)
// 128 threads = 4 warps (2x2), k32 chunks, 3-stage cp.async pipeline.
// MODE 0: plain store. MODE 1: batchnorm affine on channel (row).
// (R10-measured best configuration: occ ~30%, 78 us on qkv.)
template <int KTOT, int MODE>
__global__ void __launch_bounds__(128)
hgemm(const uint32_t* __restrict__ AH,
      const uint32_t* __restrict__ BHg,
      float* __restrict__ C, int M,
      const float* __restrict__ gamma, const float* __restrict__ beta,
      const float* __restrict__ mean,  const float* __restrict__ var)
{
    constexpr int KP   = KTOT / 2;
    constexpr int NKIT = KTOT / 32;
    constexpr int SWRD = 3456;            // A[64][20]=1280 + B[16][136]=2176
    constexpr int NSTG = 3;

    __shared__ uint32_t sm[NSTG * SWRD];  // 41472 B
    const uint32_t smb = smem_u32(sm);

    const int tid  = threadIdx.x;
    const int lane = tid & 31;
    const int warp = tid >> 5;
    const int wm   = warp >> 1;           // 0..1 -> 32 rows
    const int wn   = warp & 1;            // 0..1 -> 64 cols
    const int g    = lane >> 2;
    const int tg   = lane & 3;

    const int m0 = blockIdx.y * 64;
    const int n0 = blockIdx.x * 128;
    const uint32_t* Bh = BHg + (size_t)blockIdx.z * KP * HW;
    float*          Cb = C   + (size_t)blockIdx.z * M * HW;

    // loader roles
    const int arow = tid >> 1, aq = (tid & 1) * 8;    // A: 64 rows, 8-word halves
    const int brow = tid >> 3, bs = (tid & 7) * 16;   // B: 16 kp-rows, 16-word segs

    auto load_chunk = [&](int it, int stage) {
        const uint32_t s0 = smb + stage * SWRD * 4;
        const uint32_t* srcA = AH + (size_t)(m0 + arow) * KP + it * 16 + aq;
        uint32_t dA = s0 + (arow * 20 + aq) * 4;
        cpa16(dA,      srcA);
        cpa16(dA + 16, srcA + 4);
        const uint32_t* srcB = Bh + (size_t)(it * 16 + brow) * HW + n0 + bs;
        uint32_t dB = s0 + (1280 + brow * 136 + bs) * 4;
        #pragma unroll
        for (int q = 0; q < 4; q++) cpa16(dB + q * 16, srcB + q * 4);
    };

    load_chunk(0, 0); CPA_COMMIT();
    load_chunk(1, 1); CPA_COMMIT();

    float c[2][8][4] = {};

    for (int it = 0; it < NKIT; it++) {
        if (it + 2 < NKIT) { load_chunk(it + 2, (it + 2) % NSTG); CPA_COMMIT(); CPA_WAIT2(); }
        else if (it + 1 < NKIT) { CPA_WAIT1(); }
        else { CPA_WAIT0(); }
        __syncthreads();

        const uint32_t* sAh = sm + (it % NSTG) * SWRD;
        const uint32_t* sBh = sAh + 1280;

        #pragma unroll
        for (int ks = 0; ks < 2; ks++) {
            const int kp0 = ks * 8;
            uint32_t ah[2][4], bh[8][2];
            #pragma unroll
            for (int mt = 0; mt < 2; mt++) {
                int r = wm * 32 + mt * 16 + g;
                ah[mt][0] = sAh[r * 20 + kp0 + tg];
                ah[mt][1] = sAh[(r + 8) * 20 + kp0 + tg];
                ah[mt][2] = sAh[r * 20 + kp0 + tg + 4];
                ah[mt][3] = sAh[(r + 8) * 20 + kp0 + tg + 4];
            }
            #pragma unroll
            for (int nt = 0; nt < 8; nt++) {
                int col = wn * 64 + nt * 8 + g;
                bh[nt][0] = sBh[(kp0 + tg) * 136 + col];
                bh[nt][1] = sBh[(kp0 + tg + 4) * 136 + col];
            }
            #pragma unroll
            for (int nt = 0; nt < 8; nt++)
                #pragma unroll
                for (int mt = 0; mt < 2; mt++) mma_fp16(c[mt][nt], ah[mt], bh[nt]);
        }
        __syncthreads();
    }

    // ---- epilogue: stage C tile in smem (stride 132), coalesced writeout ----
    float* Cs = (float*)sm;               // 64*132 = 8448 w (fits in 10368)
    #pragma unroll
    for (int mt = 0; mt < 2; mt++)
        #pragma unroll
        for (int nt = 0; nt < 8; nt++) {
            int r   = wm * 32 + mt * 16 + g;
            int col = wn * 64 + nt * 8 + tg * 2;
            Cs[r * 132 + col]           = c[mt][nt][0];
            Cs[r * 132 + col + 1]       = c[mt][nt][1];
            Cs[(r + 8) * 132 + col]     = c[mt][nt][2];
            Cs[(r + 8) * 132 + col + 1] = c[mt][nt][3];
        }
    __syncthreads();

    #pragma unroll 8
    for (int i = tid; i < 8192; i += 128) {
        int r = i >> 7, n = i & 127;
        float v = Cs[r * 132 + n];
        if (MODE == 1) {
            int m = m0 + r;
            float sc = __ldg(&gamma[m]) * rsqrtf(__ldg(&var[m]) + 1e-5f);
            v = v * sc + __ldg(&beta[m]) - __ldg(&mean[m]) * sc;
        }
        Cb[(size_t)(m0 + r) * HW + n0 + n] = v;
    }
}

// ------- fused p-mix + depthwise 3x3 (SAME), 4 output rows per block --------
__global__ void __launch_bounds__(256)
pdw_kernel(const float* __restrict__ QKV,
           const float* __restrict__ Wp,
           const float* __restrict__ Wd,
           float* __restrict__ D)
{
    __shared__ float sin[8][6][WIDTH];    // 24 KB
    __shared__ float sp [8][6][WIDTH];    // 24 KB

    const int b  = blockIdx.z;
    const int gr = blockIdx.y;
    const int h0 = blockIdx.x * 4;        // output rows h0..h0+3
    const int tid = threadIdx.x;
    const float* src = QKV + ((size_t)b * CQKV + gr * 8) * HW;

    // load 8 in-channels x 6 rows (h0-1 .. h0+4, zero-padded)
    #pragma unroll
    for (int i = 0; i < 24; i++) {
        int lin = tid + i * 256;          // 0..6143
        int ch = lin / 768, rem = lin - ch * 768;
        int rs = rem >> 7, col = rem & 127;
        int row = h0 - 1 + rs;
        sin[ch][rs][col] = ((unsigned)row < (unsigned)WIDTH)
                           ? src[ch * HW + row * WIDTH + col] : 0.f;
    }
    __syncthreads();

    // mix: p[o][r][c] = sum_i Wp[gr][o][i] * in[i][r][c]
    #pragma unroll
    for (int i = 0; i < 24; i++) {
        int lin = tid + i * 256;
        int oc = lin / 768, rem = lin - oc * 768;
        int rs = rem >> 7, col = rem & 127;
        float s = 0.f;
        #pragma unroll
        for (int ic = 0; ic < 8; ic++)
            s += __ldg(&Wp[gr * 64 + oc * 8 + ic]) * sin[ic][rs][col];
        sp[oc][rs][col] = s;
    }
    __syncthreads();

    // conv: out[oc][h0+hr][col], taps from sp rows hr..hr+2
    #pragma unroll
    for (int i = 0; i < 16; i++) {
        int lin = tid + i * 256;          // 0..4095
        int oc = lin >> 9, hr = (lin >> 7) & 3, col = lin & 127;
        int c = gr * 8 + oc;
        float s = 0.f;
        #pragma unroll
        for (int ky = 0; ky < 3; ky++) {
            float w0 = __ldg(&Wd[c * 9 + ky * 3 + 0]);
            float w1 = __ldg(&Wd[c * 9 + ky * 3 + 1]);
            float w2 = __ldg(&Wd[c * 9 + ky * 3 + 2]);
            const float* row = sp[oc][hr + ky];
            if (col > 0)   s += w0 * row[col - 1];
            s += w1 * row[col];
            if (col < 127) s += w2 * row[col + 1];
        }
        D[((size_t)b * CQKV + c) * HW + (h0 + hr) * WIDTH + col] = s;
    }
}

// ---------------- kv partial sums -------------------------------------------
__global__ void __launch_bounds__(256)
kv_kernel(const float* __restrict__ QKV,
          const float* __restrict__ D,
          float* __restrict__ kvp)
{
    const int b = blockIdx.z, G = blockIdx.y, chunk = blockIdx.x;
    const int tid = threadIdx.x;
    const float* base = (G < 8) ? QKV + ((size_t)b * CQKV + G * 24) * HW
                                : D   + ((size_t)b * CQKV + (G - 8) * 24) * HW;
    float acc[72];
    #pragma unroll
    for (int i = 0; i < 72; i++) acc[i] = 0.f;

    #pragma unroll
    for (int it = 0; it < 4; it++) {
        int n = chunk * 2048 + it * 512 + tid * 2;
        float2 kr[8], vr[8];
        #pragma unroll
        for (int d = 0; d < 8; d++) {
            float2 t = *(const float2*)&base[(8 + d) * HW + n];
            kr[d].x = fmaxf(t.x, 0.f); kr[d].y = fmaxf(t.y, 0.f);
        }
        #pragma unroll
        for (int e = 0; e < 8; e++) vr[e] = *(const float2*)&base[(16 + e) * HW + n];
        #pragma unroll
        for (int d = 0; d < 8; d++) {
            #pragma unroll
            for (int e = 0; e < 8; e++)
                acc[d * 9 + e] += kr[d].x * vr[e].x + kr[d].y * vr[e].y;
            acc[d * 9 + 8] += kr[d].x + kr[d].y;
        }
    }

    __shared__ float red[8][72];
    const int lane = tid & 31, warp = tid >> 5;
    #pragma unroll
    for (int i = 0; i < 72; i++) {
        float v = acc[i];
        #pragma unroll
        for (int off = 16; off; off >>= 1) v += __shfl_down_sync(0xffffffffu, v, off);
        if (lane == 0) red[warp][i] = v;
    }
    __syncthreads();
    for (int i = tid; i < 72; i += 256) {
        float s = 0.f;
        #pragma unroll
        for (int w2 = 0; w2 < 8; w2++) s += red[w2][i];
        kvp[((size_t)(b * 16 + G) * 8 + chunk) * 72 + i] = s;
    }
}

// ------- o = normalize(relu(q)@kv), written as packed fp16 pairs ------------
// Folds the kvp chunk-reduction (deterministic, per-block in smem).
__global__ void __launch_bounds__(256)
o_kernel(const float* __restrict__ QKV,
         const float* __restrict__ D,
         const float* __restrict__ kvp,
         uint32_t* __restrict__ OH)
{
    const int b = blockIdx.y;
    __shared__ float skv[16 * 72];
    for (int i = threadIdx.x; i < 16 * 72; i += 256) {
        float s = 0.f;
        #pragma unroll
        for (int c = 0; c < 8; c++)
            s += kvp[((size_t)(b * 16 + (i / 72)) * 8 + c) * 72 + (i % 72)];
        skv[i] = s;
    }
    __syncthreads();

    const int n = blockIdx.x * 256 + threadIdx.x;
    #pragma unroll
    for (int G = 0; G < 16; G++) {
        const float* base = (G < 8) ? QKV + ((size_t)b * CQKV + G * 24) * HW
                                    : D   + ((size_t)b * CQKV + (G - 8) * 24) * HW;
        float num[8] = {};
        float den = 0.f;
        #pragma unroll
        for (int d = 0; d < 8; d++) {
            float q = fmaxf(base[d * HW + n], 0.f);
            #pragma unroll
            for (int j = 0; j < 8; j++) num[j] += q * skv[G * 72 + d * 9 + j];
            den += q * skv[G * 72 + d * 9 + 8];
        }
        float inv = 1.f / (den + 1e-15f);
        #pragma unroll
        for (int jj = 0; jj < 4; jj++) {
            size_t o = ((size_t)b * 64 + G * 4 + jj) * HW + n;
            OH[o] = hpack(num[2 * jj] * inv, num[2 * jj + 1] * inv);
        }
    }
}

// ---------------- launch --------------------------------------------------
extern "C" void kernel_launch(void* const* d_in, const int* in_sizes, int n_in,
                              void* d_out, int out_size)
{
    const float* x     = (const float*)d_in[0];
    const float* W_qkv = (const float*)d_in[1];
    const float* W_p   = (const float*)d_in[2];
    const float* W_d   = (const float*)d_in[3];
    const float* W_ffn = (const float*)d_in[4];
    const float* gamma = (const float*)d_in[5];
    const float* beta  = (const float*)d_in[6];
    const float* mean  = (const float*)d_in[7];
    const float* var   = (const float*)d_in[8];
    float* out = (float*)d_out;

    float *qkv, *d, *kvp;
    uint32_t *xh, *oh, *wqh, *wfh;
    cudaGetSymbolAddress((void**)&qkv, g_qkv);
    cudaGetSymbolAddress((void**)&d,   g_d);
    cudaGetSymbolAddress((void**)&xh,  g_xh);
    cudaGetSymbolAddress((void**)&oh,  g_oh);
    cudaGetSymbolAddress((void**)&wqh, g_wqh);
    cudaGetSymbolAddress((void**)&wfh, g_wfh);
    cudaGetSymbolAddress((void**)&kvp, g_kvp);

    // 0) operand conversions (once per call)
    wcvt_kernel<<<(CQKV * 128 + 255) / 256, 256>>>(W_qkv, wqh, CQKV * 128);
    wcvt_kernel<<<(256 * 64 + 255) / 256, 256>>>(W_ffn, wfh, 256 * 64);
    xcvt_kernel<<<NB * 128 * (HW / 4) / 256, 256>>>(x, xh);

    // 1) qkv = W_qkv @ x   (fp16 HMMA, 64x128 block, 3-stage — R10 config)
    hgemm<256, 0><<<dim3(HW / 128, CQKV / 64, NB), 128>>>(
        wqh, xh, qkv, CQKV, nullptr, nullptr, nullptr, nullptr);

    // 2) d = depthwise3x3(blockdiag(W_p) @ qkv)   (4-row strips)
    pdw_kernel<<<dim3(WIDTH / 4, 24, NB), 256>>>(qkv, W_p, W_d, d);

    // 3) kv partial sums (chunk reduction folded into o_kernel)
    kv_kernel<<<dim3(8, 16, NB), 256>>>(qkv, d, kvp);

    // 4) o = normalize(relu(q) @ kv) -> packed fp16 pairs
    o_kernel<<<dim3(HW / 256, NB), 256>>>(qkv, d, kvp, oh);

    // 5) out = BN(W_ffn @ o)   (R10 config)
    hgemm<128, 1><<<dim3(HW / 128, 256 / 64, NB), 128>>>(
        wfh, oh, out, 256, gamma, beta, mean, var);
}

// round 14
// speedup vs baseline: 1.8216x; 1.0117x over previous
#include <cuda_runtime.h>
#include <cuda_fp16.h>
#include <math.h>
#include <stdint.h>

#define HW    16384
#define WIDTH 128
#define NB    8
#define CQKV  192

// ---------------- scratch (static device allocations; no cudaMalloc) --------
__device__ float    g_qkv[NB * CQKV * HW];    // 100.7 MB
__device__ float    g_d  [NB * CQKV * HW];    // 100.7 MB
__device__ uint32_t g_xh [NB * 128 * HW];     // x packed fp16-pair (67 MB)
__device__ uint32_t g_oh [NB * 64 * HW];      // o packed fp16-pair (33.5 MB)
__device__ uint32_t g_wqh[CQKV * 128];        // qkv weights packed
__device__ uint32_t g_wfh[256 * 64];          // ffn weights packed
__device__ float    g_kvp[NB * 16 * 8 * 72];

// ---------------- fp16 helpers ----------------------------------------------
__device__ __forceinline__ uint32_t hpack(float a, float b) {
    __half2 t = __floats2half2_rn(a, b);      // .x = a (low), .y = b (high)
    return *reinterpret_cast<uint32_t*>(&t);
}
__device__ __forceinline__ void mma_fp16(float c[4], const uint32_t a[4], const uint32_t b[2]) {
    asm volatile(
        "mma.sync.aligned.m16n8k16.row.col.f32.f16.f16.f32 "
        "{%0,%1,%2,%3}, {%4,%5,%6,%7}, {%8,%9}, {%0,%1,%2,%3};\n"
        : "+f"(c[0]), "+f"(c[1]), "+f"(c[2]), "+f"(c[3])
        : "r"(a[0]), "r"(a[1]), "r"(a[2]), "r"(a[3]), "r"(b[0]), "r"(b[1]));
}
__device__ __forceinline__ uint32_t smem_u32(const void* p) {
    uint32_t a;
    asm("{ .reg .u64 t; cvta.to.shared.u64 t, %1; cvt.u32.u64 %0, t; }" : "=r"(a) : "l"(p));
    return a;
}
__device__ __forceinline__ void cpa16(uint32_t dst, const void* src) {
    asm volatile("cp.async.cg.shared.global [%0], [%1], 16;\n" :: "r"(dst), "l"(src));
}
#define CPA_COMMIT() asm volatile("cp.async.commit_group;\n" ::: "memory")
#define CPA_WAIT2()  asm volatile("cp.async.wait_group 2;\n" ::: "memory")
#define CPA_WAIT1()  asm volatile("cp.async.wait_group 1;\n" ::: "memory")
#define CPA_WAIT0()  asm volatile("cp.async.wait_group 0;\n" ::: "memory")

// ---------------- convert kernels -------------------------------------------
__global__ void wcvt_kernel(const float* __restrict__ W,
                            uint32_t* __restrict__ WH, int npairs)
{
    int i = blockIdx.x * 256 + threadIdx.x;
    if (i >= npairs) return;
    WH[i] = hpack(W[2 * i], W[2 * i + 1]);
}

// X [b][K][HW] -> packed fp16 k-pair array [b][K/2][HW]
__global__ void xcvt_kernel(const float* __restrict__ X, uint32_t* __restrict__ XH)
{
    int idx = blockIdx.x * 256 + threadIdx.x;
    int n  = (idx & 4095) * 4;
    int t  = idx >> 12;                           // b*128 + kp
    const float4 a = *(const float4*)&X[(size_t)t * 2 * HW + n];
    const float4 b = *(const float4*)&X[(size_t)t * 2 * HW + HW + n];
    uint4 w;
    w.x = hpack(a.x, b.x);
    w.y = hpack(a.y, b.y);
    w.z = hpack(a.z, b.z);
    w.w = hpack(a.w, b.w);
    *(uint4*)&XH[(size_t)t * HW + n] = w;
}

// ============ fp16 single-pass HMMA GEMM, 64x128 block, 32x64 warp tiles ====
// C[b](M x HW) = W(M x KTOT) * X[b](KTOT x HW)
// 128 threads = 4 warps (2x2), k32 chunks, 3-stage cp.async pipeline.
// MODE 0: plain store. MODE 1: batchnorm affine on channel (row).
// (R10/R13-measured best configuration — DO NOT perturb.)
template <int KTOT, int MODE>
__global__ void __launch_bounds__(128)
hgemm(const uint32_t* __restrict__ AH,
      const uint32_t* __restrict__ BHg,
      float* __restrict__ C, int M,
      const float* __restrict__ gamma, const float* __restrict__ beta,
      const float* __restrict__ mean,  const float* __restrict__ var)
{
    constexpr int KP   = KTOT / 2;
    constexpr int NKIT = KTOT / 32;
    constexpr int SWRD = 3456;            // A[64][20]=1280 + B[16][136]=2176
    constexpr int NSTG = 3;

    __shared__ uint32_t sm[NSTG * SWRD];  // 41472 B
    const uint32_t smb = smem_u32(sm);

    const int tid  = threadIdx.x;
    const int lane = tid & 31;
    const int warp = tid >> 5;
    const int wm   = warp >> 1;           // 0..1 -> 32 rows
    const int wn   = warp & 1;            // 0..1 -> 64 cols
    const int g    = lane >> 2;
    const int tg   = lane & 3;

    const int m0 = blockIdx.y * 64;
    const int n0 = blockIdx.x * 128;
    const uint32_t* Bh = BHg + (size_t)blockIdx.z * KP * HW;
    float*          Cb = C   + (size_t)blockIdx.z * M * HW;

    // loader roles
    const int arow = tid >> 1, aq = (tid & 1) * 8;    // A: 64 rows, 8-word halves
    const int brow = tid >> 3, bs = (tid & 7) * 16;   // B: 16 kp-rows, 16-word segs

    auto load_chunk = [&](int it, int stage) {
        const uint32_t s0 = smb + stage * SWRD * 4;
        const uint32_t* srcA = AH + (size_t)(m0 + arow) * KP + it * 16 + aq;
        uint32_t dA = s0 + (arow * 20 + aq) * 4;
        cpa16(dA,      srcA);
        cpa16(dA + 16, srcA + 4);
        const uint32_t* srcB = Bh + (size_t)(it * 16 + brow) * HW + n0 + bs;
        uint32_t dB = s0 + (1280 + brow * 136 + bs) * 4;
        #pragma unroll
        for (int q = 0; q < 4; q++) cpa16(dB + q * 16, srcB + q * 4);
    };

    load_chunk(0, 0); CPA_COMMIT();
    load_chunk(1, 1); CPA_COMMIT();

    float c[2][8][4] = {};

    for (int it = 0; it < NKIT; it++) {
        if (it + 2 < NKIT) { load_chunk(it + 2, (it + 2) % NSTG); CPA_COMMIT(); CPA_WAIT2(); }
        else if (it + 1 < NKIT) { CPA_WAIT1(); }
        else { CPA_WAIT0(); }
        __syncthreads();

        const uint32_t* sAh = sm + (it % NSTG) * SWRD;
        const uint32_t* sBh = sAh + 1280;

        #pragma unroll
        for (int ks = 0; ks < 2; ks++) {
            const int kp0 = ks * 8;
            uint32_t ah[2][4], bh[8][2];
            #pragma unroll
            for (int mt = 0; mt < 2; mt++) {
                int r = wm * 32 + mt * 16 + g;
                ah[mt][0] = sAh[r * 20 + kp0 + tg];
                ah[mt][1] = sAh[(r + 8) * 20 + kp0 + tg];
                ah[mt][2] = sAh[r * 20 + kp0 + tg + 4];
                ah[mt][3] = sAh[(r + 8) * 20 + kp0 + tg + 4];
            }
            #pragma unroll
            for (int nt = 0; nt < 8; nt++) {
                int col = wn * 64 + nt * 8 + g;
                bh[nt][0] = sBh[(kp0 + tg) * 136 + col];
                bh[nt][1] = sBh[(kp0 + tg + 4) * 136 + col];
            }
            #pragma unroll
            for (int nt = 0; nt < 8; nt++)
                #pragma unroll
                for (int mt = 0; mt < 2; mt++) mma_fp16(c[mt][nt], ah[mt], bh[nt]);
        }
        __syncthreads();
    }

    // ---- epilogue: stage C tile in smem (stride 132), coalesced writeout ----
    float* Cs = (float*)sm;               // 64*132 = 8448 w (fits in 10368)
    #pragma unroll
    for (int mt = 0; mt < 2; mt++)
        #pragma unroll
        for (int nt = 0; nt < 8; nt++) {
            int r   = wm * 32 + mt * 16 + g;
            int col = wn * 64 + nt * 8 + tg * 2;
            Cs[r * 132 + col]           = c[mt][nt][0];
            Cs[r * 132 + col + 1]       = c[mt][nt][1];
            Cs[(r + 8) * 132 + col]     = c[mt][nt][2];
            Cs[(r + 8) * 132 + col + 1] = c[mt][nt][3];
        }
    __syncthreads();

    #pragma unroll 8
    for (int i = tid; i < 8192; i += 128) {
        int r = i >> 7, n = i & 127;
        float v = Cs[r * 132 + n];
        if (MODE == 1) {
            int m = m0 + r;
            float sc = __ldg(&gamma[m]) * rsqrtf(__ldg(&var[m]) + 1e-5f);
            v = v * sc + __ldg(&beta[m]) - __ldg(&mean[m]) * sc;
        }
        Cb[(size_t)(m0 + r) * HW + n0 + n] = v;
    }
}

// ------- fused p-mix + depthwise 3x3 (SAME), 4 output rows per block --------
__global__ void __launch_bounds__(256)
pdw_kernel(const float* __restrict__ QKV,
           const float* __restrict__ Wp,
           const float* __restrict__ Wd,
           float* __restrict__ D)
{
    __shared__ float sin[8][6][WIDTH];    // 24 KB
    __shared__ float sp [8][6][WIDTH];    // 24 KB

    const int b  = blockIdx.z;
    const int gr = blockIdx.y;
    const int h0 = blockIdx.x * 4;        // output rows h0..h0+3
    const int tid = threadIdx.x;
    const float* src = QKV + ((size_t)b * CQKV + gr * 8) * HW;

    // load 8 in-channels x 6 rows (h0-1 .. h0+4, zero-padded)
    #pragma unroll
    for (int i = 0; i < 24; i++) {
        int lin = tid + i * 256;          // 0..6143
        int ch = lin / 768, rem = lin - ch * 768;
        int rs = rem >> 7, col = rem & 127;
        int row = h0 - 1 + rs;
        sin[ch][rs][col] = ((unsigned)row < (unsigned)WIDTH)
                           ? src[ch * HW + row * WIDTH + col] : 0.f;
    }
    __syncthreads();

    // mix: p[o][r][c] = sum_i Wp[gr][o][i] * in[i][r][c]
    #pragma unroll
    for (int i = 0; i < 24; i++) {
        int lin = tid + i * 256;
        int oc = lin / 768, rem = lin - oc * 768;
        int rs = rem >> 7, col = rem & 127;
        float s = 0.f;
        #pragma unroll
        for (int ic = 0; ic < 8; ic++)
            s += __ldg(&Wp[gr * 64 + oc * 8 + ic]) * sin[ic][rs][col];
        sp[oc][rs][col] = s;
    }
    __syncthreads();

    // conv: out[oc][h0+hr][col], taps from sp rows hr..hr+2
    #pragma unroll
    for (int i = 0; i < 16; i++) {
        int lin = tid + i * 256;          // 0..4095
        int oc = lin >> 9, hr = (lin >> 7) & 3, col = lin & 127;
        int c = gr * 8 + oc;
        float s = 0.f;
        #pragma unroll
        for (int ky = 0; ky < 3; ky++) {
            float w0 = __ldg(&Wd[c * 9 + ky * 3 + 0]);
            float w1 = __ldg(&Wd[c * 9 + ky * 3 + 1]);
            float w2 = __ldg(&Wd[c * 9 + ky * 3 + 2]);
            const float* row = sp[oc][hr + ky];
            if (col > 0)   s += w0 * row[col - 1];
            s += w1 * row[col];
            if (col < 127) s += w2 * row[col + 1];
        }
        D[((size_t)b * CQKV + c) * HW + (h0 + hr) * WIDTH + col] = s;
    }
}

// ---------------- kv partial sums (float4 loads, 4 px/thread/row) -----------
__global__ void __launch_bounds__(256)
kv_kernel(const float* __restrict__ QKV,
          const float* __restrict__ D,
          float* __restrict__ kvp)
{
    const int b = blockIdx.z, G = blockIdx.y, chunk = blockIdx.x;
    const int tid = threadIdx.x;
    const float* base = (G < 8) ? QKV + ((size_t)b * CQKV + G * 24) * HW
                                : D   + ((size_t)b * CQKV + (G - 8) * 24) * HW;
    float acc[72];
    #pragma unroll
    for (int i = 0; i < 72; i++) acc[i] = 0.f;

    #pragma unroll
    for (int it = 0; it < 2; it++) {
        int n = chunk * 2048 + it * 1024 + tid * 4;
        float4 kr[8], vr[8];
        #pragma unroll
        for (int d = 0; d < 8; d++) {
            float4 t = *(const float4*)&base[(8 + d) * HW + n];
            kr[d].x = fmaxf(t.x, 0.f); kr[d].y = fmaxf(t.y, 0.f);
            kr[d].z = fmaxf(t.z, 0.f); kr[d].w = fmaxf(t.w, 0.f);
        }
        #pragma unroll
        for (int e = 0; e < 8; e++) vr[e] = *(const float4*)&base[(16 + e) * HW + n];
        #pragma unroll
        for (int d = 0; d < 8; d++) {
            #pragma unroll
            for (int e = 0; e < 8; e++)
                acc[d * 9 + e] += kr[d].x * vr[e].x + kr[d].y * vr[e].y
                                + kr[d].z * vr[e].z + kr[d].w * vr[e].w;
            acc[d * 9 + 8] += kr[d].x + kr[d].y + kr[d].z + kr[d].w;
        }
    }

    __shared__ float red[8][72];
    const int lane = tid & 31, warp = tid >> 5;
    #pragma unroll
    for (int i = 0; i < 72; i++) {
        float v = acc[i];
        #pragma unroll
        for (int off = 16; off; off >>= 1) v += __shfl_down_sync(0xffffffffu, v, off);
        if (lane == 0) red[warp][i] = v;
    }
    __syncthreads();
    for (int i = tid; i < 72; i += 256) {
        float s = 0.f;
        #pragma unroll
        for (int w2 = 0; w2 < 8; w2++) s += red[w2][i];
        kvp[((size_t)(b * 16 + G) * 8 + chunk) * 72 + i] = s;
    }
}

// ------- o = normalize(relu(q)@kv), 2 px/thread, packed fp16 output ---------
// Folds the kvp chunk-reduction (deterministic, per-block in smem).
__global__ void __launch_bounds__(256)
o_kernel(const float* __restrict__ QKV,
         const float* __restrict__ D,
         const float* __restrict__ kvp,
         uint32_t* __restrict__ OH)
{
    const int b = blockIdx.y;
    __shared__ float skv[16 * 72];
    for (int i = threadIdx.x; i < 16 * 72; i += 256) {
        float s = 0.f;
        #pragma unroll
        for (int c = 0; c < 8; c++)
            s += kvp[((size_t)(b * 16 + (i / 72)) * 8 + c) * 72 + (i % 72)];
        skv[i] = s;
    }
    __syncthreads();

    const int n = blockIdx.x * 512 + threadIdx.x * 2;
    #pragma unroll
    for (int G = 0; G < 16; G++) {
        const float* base = (G < 8) ? QKV + ((size_t)b * CQKV + G * 24) * HW
                                    : D   + ((size_t)b * CQKV + (G - 8) * 24) * HW;
        float2 num[8];
        #pragma unroll
        for (int j = 0; j < 8; j++) num[j] = make_float2(0.f, 0.f);
        float2 den = make_float2(0.f, 0.f);
        #pragma unroll
        for (int d = 0; d < 8; d++) {
            float2 t = *(const float2*)&base[d * HW + n];
            float qx = fmaxf(t.x, 0.f), qy = fmaxf(t.y, 0.f);
            #pragma unroll
            for (int j = 0; j < 8; j++) {
                float w = skv[G * 72 + d * 9 + j];
                num[j].x += qx * w;
                num[j].y += qy * w;
            }
            float w8 = skv[G * 72 + d * 9 + 8];
            den.x += qx * w8;
            den.y += qy * w8;
        }
        float invx = 1.f / (den.x + 1e-15f);
        float invy = 1.f / (den.y + 1e-15f);
        #pragma unroll
        for (int jj = 0; jj < 4; jj++) {
            uint2 w;
            w.x = hpack(num[2 * jj].x * invx, num[2 * jj + 1].x * invx);
            w.y = hpack(num[2 * jj].y * invy, num[2 * jj + 1].y * invy);
            *(uint2*)&OH[((size_t)b * 64 + G * 4 + jj) * HW + n] = w;
        }
    }
}

// ---------------- launch --------------------------------------------------
extern "C" void kernel_launch(void* const* d_in, const int* in_sizes, int n_in,
                              void* d_out, int out_size)
{
    const float* x     = (const float*)d_in[0];
    const float* W_qkv = (const float*)d_in[1];
    const float* W_p   = (const float*)d_in[2];
    const float* W_d   = (const float*)d_in[3];
    const float* W_ffn = (const float*)d_in[4];
    const float* gamma = (const float*)d_in[5];
    const float* beta  = (const float*)d_in[6];
    const float* mean  = (const float*)d_in[7];
    const float* var   = (const float*)d_in[8];
    float* out = (float*)d_out;

    float *qkv, *d, *kvp;
    uint32_t *xh, *oh, *wqh, *wfh;
    cudaGetSymbolAddress((void**)&qkv, g_qkv);
    cudaGetSymbolAddress((void**)&d,   g_d);
    cudaGetSymbolAddress((void**)&xh,  g_xh);
    cudaGetSymbolAddress((void**)&oh,  g_oh);
    cudaGetSymbolAddress((void**)&wqh, g_wqh);
    cudaGetSymbolAddress((void**)&wfh, g_wfh);
    cudaGetSymbolAddress((void**)&kvp, g_kvp);

    // 0) operand conversions (once per call)
    wcvt_kernel<<<(CQKV * 128 + 255) / 256, 256>>>(W_qkv, wqh, CQKV * 128);
    wcvt_kernel<<<(256 * 64 + 255) / 256, 256>>>(W_ffn, wfh, 256 * 64);
    xcvt_kernel<<<NB * 128 * (HW / 4) / 256, 256>>>(x, xh);

    // 1) qkv = W_qkv @ x   (fp16 HMMA, 64x128 block, 3-stage — R10 config)
    hgemm<256, 0><<<dim3(HW / 128, CQKV / 64, NB), 128>>>(
        wqh, xh, qkv, CQKV, nullptr, nullptr, nullptr, nullptr);

    // 2) d = depthwise3x3(blockdiag(W_p) @ qkv)   (4-row strips)
    pdw_kernel<<<dim3(WIDTH / 4, 24, NB), 256>>>(qkv, W_p, W_d, d);

    // 3) kv partial sums (float4 loads)
    kv_kernel<<<dim3(8, 16, NB), 256>>>(qkv, d, kvp);

    // 4) o = normalize(relu(q) @ kv) -> packed fp16 pairs (2 px/thread)
    o_kernel<<<dim3(HW / 512, NB), 256>>>(qkv, d, kvp, oh);

    // 5) out = BN(W_ffn @ o)   (R10 config)
    hgemm<128, 1><<<dim3(HW / 128, 256 / 64, NB), 128>>>(
        wfh, oh, out, 256, gamma, beta, mean, var);
}